// round 13
// baseline (speedup 1.0000x reference)
#include <cuda_runtime.h>
#include <cuda_bf16.h>
#include <cuda_fp16.h>
#include <math.h>

#define D 128
#define NMAX 50048
#define EMAX 960000
#define SLOPE 0.01f

// ---------------- static device scratch ----------------
__device__ unsigned int g_zero3[3 * NMAX + 32];
__device__ float g_dg[NMAX];
__device__ float g_dinv[NMAX];
__device__ int   g_ptr[NMAX + 1];
__device__ int   g_bsum[1024];
__device__ uint4 g_edges[EMAX];      // {col, wG, wS, pad}
__device__ uint4 g_xh [NMAX * 16];   // X fp16: node row = 16 x uint4 (8 feats/lane)
__device__ uint4 g_cx1[NMAX * 16];   // GCN chain fp16
__device__ uint4 g_cx2[NMAX * 16];
__device__ uint4 g_cx3[NMAX * 16];
__device__ uint4 g_cs1[NMAX * 16];   // SCT chain fp16
__device__ uint4 g_cs2[NMAX * 16];
__device__ uint4 g_cs3[NMAX * 16];
__device__ uint4 g_d1h[NMAX * 16];   // fp16 SCT diffs
__device__ uint4 g_d2h[NMAX * 16];
__device__ uint4 g_d3h[NMAX * 16];

__device__ __forceinline__ float* degp() { return (float*)g_zero3; }
__device__ __forceinline__ int*   cntp() { return (int*)(g_zero3 + NMAX); }
__device__ __forceinline__ int*   curp() { return (int*)(g_zero3 + 2 * NMAX); }
__device__ __forceinline__ int*   syncp(){ return (int*)(g_zero3 + 3 * NMAX); }

__device__ __forceinline__ int fptr(int i, int N) {
    return (i >= N) ? g_ptr[N] : (g_ptr[i] + g_bsum[i >> 9]);
}

// ---------------- helpers ----------------
__device__ __forceinline__ float lrelu(float v) { return v > 0.0f ? v : v * SLOPE; }
__device__ __forceinline__ float rlu(float v)   { return v > 0.0f ? v : 0.0f; }

__device__ __forceinline__ float wsum(float v) {
    #pragma unroll
    for (int o = 16; o > 0; o >>= 1) v += __shfl_xor_sync(0xffffffffu, v, o);
    return v;
}
__device__ __forceinline__ unsigned int pack_h2(float x, float y) {
    __half2 a = __floats2half2_rn(x, y);
    return *(unsigned int*)&a;
}
__device__ __forceinline__ float2 unpack_h2(unsigned int u) {
    __half2 a = *(__half2*)&u;
    return __half22float2(a);
}
__device__ __forceinline__ uint2 pack_h4u2(float4 v) {
    uint2 r;
    r.x = pack_h2(v.x, v.y);
    r.y = pack_h2(v.z, v.w);
    return r;
}
__device__ __forceinline__ float4 unpack_h4(uint2 u) {
    float2 fa = unpack_h2(u.x), fb = unpack_h2(u.y);
    return make_float4(fa.x, fa.y, fb.x, fb.y);
}
__device__ __forceinline__ unsigned long long pack2(float x, float y) {
    unsigned long long r;
    asm("mov.b64 %0, {%1, %2};" : "=l"(r) : "f"(x), "f"(y));
    return r;
}
__device__ __forceinline__ unsigned long long dup2(float x) {
    unsigned long long r;
    asm("mov.b64 %0, {%1, %1};" : "=l"(r) : "f"(x));
    return r;
}
__device__ __forceinline__ void fma2(unsigned long long &d, unsigned long long a, unsigned long long b) {
    asm("fma.rn.f32x2 %0, %1, %2, %0;" : "+l"(d) : "l"(a), "l"(b));
}
__device__ __forceinline__ float2 unpack2(unsigned long long v) {
    float2 r;
    asm("mov.b64 {%0, %1}, %2;" : "=f"(r.x), "=f"(r.y) : "l"(v));
    return r;
}
__device__ __forceinline__ void acc8f(float4 &A, float4 &B, uint4 u, float w) {
    float2 f0 = unpack_h2(u.x), f1 = unpack_h2(u.y);
    float2 f2 = unpack_h2(u.z), f3 = unpack_h2(u.w);
    A.x += w*f0.x; A.y += w*f0.y; A.z += w*f1.x; A.w += w*f1.y;
    B.x += w*f2.x; B.y += w*f2.y; B.z += w*f3.x; B.w += w*f3.y;
}

// ---------------- setup: degree atomics + X->fp16, fused (grid split) ----------------
__global__ void k_deg_xh(const int* __restrict__ row, const int* __restrict__ col,
                         const float* __restrict__ w, const float4* __restrict__ X,
                         int E, int NL, int eb) {
    int b = blockIdx.x;
    if (b < eb) {
        int e = b * 256 + threadIdx.x;
        if (e < E) {
            atomicAdd(&degp()[col[e]], w[e]);
            atomicAdd(&cntp()[row[e]], 1);
        }
    } else {
        int i = (b - eb) * 256 + threadIdx.x;
        if (i < NL) ((uint2*)g_xh)[i] = pack_h4u2(X[i]);
    }
}

// ---------------- fused 2-level scan (last-block finalize, parallel) ----------------
__global__ void k_scan12(int N, int nb) {
    __shared__ int sd[512];
    __shared__ int isLast;
    int tid = threadIdx.x;
    int i = blockIdx.x * 512 + tid;
    if (i < N) {
        float d = degp()[i];
        g_dg[i]   = rsqrtf(d + 1.0f);
        g_dinv[i] = 1.0f / d;
    }
    int v = (i < N) ? cntp()[i] : 0;
    sd[tid] = v;
    __syncthreads();
    #pragma unroll
    for (int off = 1; off < 512; off <<= 1) {
        int t = (tid >= off) ? sd[tid - off] : 0;
        __syncthreads();
        sd[tid] += t;
        __syncthreads();
    }
    if (i < N) g_ptr[i] = sd[tid] - v;
    if (tid == 511) g_bsum[blockIdx.x] = sd[511];
    __threadfence();
    if (tid == 0) {
        int old = atomicAdd(syncp(), 1);
        isLast = (old == nb - 1) ? 1 : 0;
    }
    __syncthreads();
    if (isLast) {
        int v2 = (tid < nb) ? g_bsum[tid] : 0;
        sd[tid] = v2;
        __syncthreads();
        #pragma unroll
        for (int off = 1; off < 512; off <<= 1) {
            int t = (tid >= off) ? sd[tid - off] : 0;
            __syncthreads();
            sd[tid] += t;
            __syncthreads();
        }
        if (tid < nb) g_bsum[tid] = sd[tid] - v2;
        if (tid == nb - 1) g_ptr[N] = sd[tid];
    }
}

__global__ void k_scatter(const int* __restrict__ row, const int* __restrict__ col,
                          const float* __restrict__ w, int E, int N) {
    int e = blockIdx.x * blockDim.x + threadIdx.x;
    if (e >= E) return;
    int r = row[e], c = col[e];
    int pos = fptr(r, N) + atomicAdd(&curp()[r], 1);
    float wv = w[e];
    uint4 v;
    v.x = (unsigned int)c;
    v.y = __float_as_uint(wv * g_dg[c]);
    v.z = __float_as_uint(wv * g_dinv[c]);
    v.w = 0u;
    g_edges[pos] = v;
}

// half-warp single-chain gather, 8-wide unroll (WSEL: 1=wG, 2=wS)
template<int WSEL>
__device__ __forceinline__ void gatherHW(const uint4* __restrict__ src, int s, int e,
                                         int l, bool act, float4 &A, float4 &B) {
    int mx = act ? (e - s) : 0;
    int mo = __shfl_xor_sync(0xffffffffu, mx, 16);
    if (mo > mx) mx = mo;
    for (int k = 0; k < mx; k += 8) {
        int i0 = s + k;
        bool vv[8];
        uint4 ee[8];
        #pragma unroll
        for (int t = 0; t < 8; t++) {
            vv[t] = act && (i0 + t < e);
            ee[t] = __ldg(&g_edges[vv[t] ? i0 + t : s]);
        }
        uint4 uu[8];
        #pragma unroll
        for (int t = 0; t < 8; t++) uu[t] = __ldg(&src[(int)ee[t].x * 16 + l]);
        #pragma unroll
        for (int t = 0; t < 8; t++) {
            float w = vv[t] ? __uint_as_float(WSEL == 1 ? ee[t].y : ee[t].z) : 0.f;
            acc8f(A, B, uu[t], w);
        }
    }
}

// ---------------- pass 1: split-chain; warp0 = GCN from xh, warp1 = SCT from xh ----------------
__global__ __launch_bounds__(64, 12)
void k_pass1(const float4* __restrict__ X, int N) {
    int warp = threadIdx.x >> 5;
    int lane = threadIdx.x & 31;
    int half = lane >> 4, l = lane & 15;
    int n = blockIdx.x * 2 + half;
    bool act = (n < N);
    int nn = act ? n : 0;
    int s = fptr(nn, N), e = fptr(nn + 1, N);
    float4 A = make_float4(0,0,0,0), B = make_float4(0,0,0,0);

    if (warp == 0) {
        gatherHW<1>(g_xh, s, e, l, act, A, B);
        if (act) {
            float dg = g_dg[n];
            float4 x0 = X[n * 32 + 2 * l];
            float4 x1 = X[n * 32 + 2 * l + 1];
            uint4 cx;
            cx.x = pack_h2((A.x + x0.x*dg)*dg, (A.y + x0.y*dg)*dg);
            cx.y = pack_h2((A.z + x0.z*dg)*dg, (A.w + x0.w*dg)*dg);
            cx.z = pack_h2((B.x + x1.x*dg)*dg, (B.y + x1.y*dg)*dg);
            cx.w = pack_h2((B.z + x1.z*dg)*dg, (B.w + x1.w*dg)*dg);
            g_cx1[n * 16 + l] = cx;
        }
    } else {
        gatherHW<2>(g_xh, s, e, l, act, A, B);
        if (act) {
            float4 x0 = X[n * 32 + 2 * l];
            float4 x1 = X[n * 32 + 2 * l + 1];
            uint4 cs;
            cs.x = pack_h2(0.5f*(x0.x + A.x), 0.5f*(x0.y + A.y));
            cs.y = pack_h2(0.5f*(x0.z + A.z), 0.5f*(x0.w + A.w));
            cs.z = pack_h2(0.5f*(x1.x + B.x), 0.5f*(x1.y + B.y));
            cs.w = pack_h2(0.5f*(x1.z + B.z), 0.5f*(x1.w + B.w));
            g_cs1[n * 16 + l] = cs;
        }
    }
}

// ---------------- mid pass: warp0 = GCN chain (2 nodes), warp1 = SCT chain (2 nodes) ----------------
__global__ __launch_bounds__(64, 12)
void k_mid(const uint4* __restrict__ xin, const uint4* __restrict__ sin_,
           uint4* __restrict__ xout, uint4* __restrict__ sout,
           uint4* __restrict__ dout, int N) {
    int warp = threadIdx.x >> 5;
    int lane = threadIdx.x & 31;
    int half = lane >> 4, l = lane & 15;
    int n = blockIdx.x * 2 + half;
    bool act = (n < N);
    int nn = act ? n : 0;
    int s = fptr(nn, N), e = fptr(nn + 1, N);
    float4 A = make_float4(0,0,0,0), B = make_float4(0,0,0,0);

    if (warp == 0) {
        gatherHW<1>(xin, s, e, l, act, A, B);
        if (act) {
            float dg = g_dg[n];
            uint4 xg = xin[n * 16 + l];
            float2 f0 = unpack_h2(xg.x), f1 = unpack_h2(xg.y);
            float2 f2 = unpack_h2(xg.z), f3 = unpack_h2(xg.w);
            uint4 cx;
            cx.x = pack_h2((A.x + f0.x*dg)*dg, (A.y + f0.y*dg)*dg);
            cx.y = pack_h2((A.z + f1.x*dg)*dg, (A.w + f1.y*dg)*dg);
            cx.z = pack_h2((B.x + f2.x*dg)*dg, (B.y + f2.y*dg)*dg);
            cx.w = pack_h2((B.z + f3.x*dg)*dg, (B.w + f3.y*dg)*dg);
            xout[n * 16 + l] = cx;
        }
    } else {
        gatherHW<2>(sin_, s, e, l, act, A, B);
        if (act) {
            uint4 sg = sin_[n * 16 + l];
            float2 f0 = unpack_h2(sg.x), f1 = unpack_h2(sg.y);
            float2 f2 = unpack_h2(sg.z), f3 = unpack_h2(sg.w);
            uint4 cs, d;
            cs.x = pack_h2(0.5f*(f0.x + A.x), 0.5f*(f0.y + A.y));
            cs.y = pack_h2(0.5f*(f1.x + A.z), 0.5f*(f1.y + A.w));
            cs.z = pack_h2(0.5f*(f2.x + B.x), 0.5f*(f2.y + B.y));
            cs.w = pack_h2(0.5f*(f3.x + B.z), 0.5f*(f3.y + B.w));
            d.x  = pack_h2(0.5f*(f0.x - A.x), 0.5f*(f0.y - A.y));
            d.y  = pack_h2(0.5f*(f1.x - A.z), 0.5f*(f1.y - A.w));
            d.z  = pack_h2(0.5f*(f2.x - B.x), 0.5f*(f2.y - B.y));
            d.w  = pack_h2(0.5f*(f3.x - B.z), 0.5f*(f3.y - B.w));
            sout[n * 16 + l] = cs;
            dout[n * 16 + l] = d;
        }
    }
}

// ---------------- final pass: half-warp layout, gather cs3 -> d3 ----------------
__global__ __launch_bounds__(64, 12)
void k_pass4(const uint4* __restrict__ sh, uint4* __restrict__ dout, int N) {
    int lane = threadIdx.x & 31;
    int gw = blockIdx.x * 2 + (threadIdx.x >> 5);
    int half = lane >> 4, l = lane & 15;
    int n = gw * 2 + half;
    bool act = (n < N);
    int nn = act ? n : 0;
    int s = fptr(nn, N), e = fptr(nn + 1, N);
    float4 A = make_float4(0,0,0,0), B = make_float4(0,0,0,0);
    gatherHW<2>(sh, s, e, l, act, A, B);
    if (act) {
        uint4 sg = sh[n * 16 + l];
        float2 f0 = unpack_h2(sg.x), f1 = unpack_h2(sg.y);
        float2 f2 = unpack_h2(sg.z), f3 = unpack_h2(sg.w);
        uint4 d;
        d.x = pack_h2(0.5f*(f0.x - A.x), 0.5f*(f0.y - A.y));
        d.y = pack_h2(0.5f*(f1.x - A.z), 0.5f*(f1.y - A.w));
        d.z = pack_h2(0.5f*(f2.x - B.x), 0.5f*(f2.y - B.y));
        d.w = pack_h2(0.5f*(f3.x - B.z), 0.5f*(f3.y - B.w));
        dout[n * 16 + l] = d;
    }
}

// ---------------- fused epilogue: 64-row tiles, 2 blocks/SM ----------------
__device__ __forceinline__ float4 lrelu4(float4 v) {
    return make_float4(lrelu(v.x), lrelu(v.y), lrelu(v.z), lrelu(v.w));
}
__device__ __forceinline__ float apw(float d, bool is1, float mf) {
    float a = fabsf(d);
    return is1 ? a : __powf(a, mf);
}

__device__ __forceinline__ void wtrans(const float* __restrict__ W, float* Wt,
                                       float stage[32][33], int tid) {
    int tx = tid & 31, ty0 = tid >> 5;
    for (int t = 0; t < 16; t++) {
        int ko = (t >> 2) << 5, oo = (t & 3) << 5;
        #pragma unroll
        for (int i = 0; i < 4; i++) {
            int ty = ty0 + i * 8;
            stage[ty][tx] = W[(oo + ty) * D + ko + tx];
        }
        __syncthreads();
        #pragma unroll
        for (int i = 0; i < 4; i++) {
            int ty = ty0 + i * 8;
            Wt[(ko + ty) * D + oo + tx] = stage[tx][ty];
        }
        __syncthreads();
    }
}

__device__ __forceinline__ void gemm_core8(const float* hs, const float* Wt,
                                           int wid, int lane, unsigned long long acc[8][2]) {
    int o4 = lane << 2;
    #pragma unroll
    for (int r = 0; r < 8; r++) { acc[r][0] = 0ull; acc[r][1] = 0ull; }
    for (int k4 = 0; k4 < 32; k4++) {
        unsigned long long wp[4][2];
        #pragma unroll
        for (int kk = 0; kk < 4; kk++) {
            float4 wv = *(const float4*)&Wt[(k4 * 4 + kk) * D + o4];
            wp[kk][0] = pack2(wv.x, wv.y);
            wp[kk][1] = pack2(wv.z, wv.w);
        }
        #pragma unroll
        for (int r = 0; r < 8; r++) {
            float4 h4 = *(const float4*)&hs[(wid * 8 + r) * D + k4 * 4];
            unsigned long long hp;
            hp = dup2(h4.x); fma2(acc[r][0], hp, wp[0][0]); fma2(acc[r][1], hp, wp[0][1]);
            hp = dup2(h4.y); fma2(acc[r][0], hp, wp[1][0]); fma2(acc[r][1], hp, wp[1][1]);
            hp = dup2(h4.z); fma2(acc[r][0], hp, wp[2][0]); fma2(acc[r][1], hp, wp[2][1]);
            hp = dup2(h4.w); fma2(acc[r][0], hp, wp[3][0]); fma2(acc[r][1], hp, wp[3][1]);
        }
    }
}

extern __shared__ float dsm[];
__global__ __launch_bounds__(256, 2)
void k_epilogue(const float4* __restrict__ X, const float4* __restrict__ a4,
                const int* __restrict__ mom,
                const float* __restrict__ W1, const float* __restrict__ b1,
                const float* __restrict__ W2, const float* __restrict__ b2,
                float* __restrict__ out, int N) {
    float* Wt = dsm;            // 16384 floats (64KB)
    float* hs = dsm + 16384;    // 8192 floats (32KB): 64 rows x 128
    __shared__ float stage[32][33];

    int tid = threadIdx.x, wid = tid >> 5, lane = tid & 31;
    int row0 = blockIdx.x * 64;
    float4* hs4 = (float4*)hs;

    const uint2* cx1 = (const uint2*)g_cx1;
    const uint2* cx2 = (const uint2*)g_cx2;
    const uint2* cx3 = (const uint2*)g_cx3;
    const uint2* d1p = (const uint2*)g_d1h;
    const uint2* d2p = (const uint2*)g_d2h;
    const uint2* d3p = (const uint2*)g_d3h;

    float4 aX = a4[lane];
    float4 aH = a4[32 + lane];
    int mi = mom[0];
    bool is1 = (mi == 1) || (__int_as_float(mi) == 1.0f);
    float mf = 1.0f;
    if (!is1) mf = (mi > 0 && mi < 64) ? (float)mi : __int_as_float(mi);

    // Phase A: attention -> hs (8 rows per warp)
    for (int r = 0; r < 8; r++) {
        int n = row0 + wid * 8 + r;
        float4 o = make_float4(0.f, 0.f, 0.f, 0.f);
        if (n < N) {
            int base = n * 32 + lane;
            float4 xr = X[base];
            float eX = wsum(rlu(xr.x)*aX.x + rlu(xr.y)*aX.y + rlu(xr.z)*aX.z + rlu(xr.w)*aX.w);

            float4 h[6];
            h[0] = lrelu4(unpack_h4(cx1[base]));
            h[1] = lrelu4(unpack_h4(cx2[base]));
            h[2] = lrelu4(unpack_h4(cx3[base]));
            float4 d1 = unpack_h4(d1p[base]);
            float4 d2 = unpack_h4(d2p[base]);
            float4 d3 = unpack_h4(d3p[base]);
            h[3] = make_float4(apw(d1.x,is1,mf), apw(d1.y,is1,mf), apw(d1.z,is1,mf), apw(d1.w,is1,mf));
            h[4] = make_float4(apw(d2.x,is1,mf), apw(d2.y,is1,mf), apw(d2.z,is1,mf), apw(d2.w,is1,mf));
            h[5] = make_float4(apw(d3.x,is1,mf), apw(d3.y,is1,mf), apw(d3.z,is1,mf), apw(d3.w,is1,mf));

            float e[6];
            #pragma unroll
            for (int c = 0; c < 6; c++) {
                float part = rlu(h[c].x)*aH.x + rlu(h[c].y)*aH.y + rlu(h[c].z)*aH.z + rlu(h[c].w)*aH.w;
                e[c] = eX + wsum(part);
            }
            float mx = e[0];
            #pragma unroll
            for (int c = 1; c < 6; c++) mx = fmaxf(mx, e[c]);
            float at[6], s = 0.f;
            #pragma unroll
            for (int c = 0; c < 6; c++) { at[c] = __expf(e[c] - mx); s += at[c]; }
            float inv = 1.0f / (6.0f * s);
            #pragma unroll
            for (int c = 0; c < 6; c++) {
                o.x += at[c]*h[c].x; o.y += at[c]*h[c].y; o.z += at[c]*h[c].z; o.w += at[c]*h[c].w;
            }
            o.x *= inv; o.y *= inv; o.z *= inv; o.w *= inv;
        }
        hs4[(wid * 8 + r) * 32 + lane] = o;
    }
    __syncthreads();

    // Phase B: GEMM1 -> hs in place
    wtrans(W1, Wt, stage, tid);
    unsigned long long acc[8][2];
    gemm_core8(hs, Wt, wid, lane, acc);
    __syncthreads();
    {
        int o4 = lane << 2;
        float4 bb = *(const float4*)&b1[o4];
        #pragma unroll
        for (int r = 0; r < 8; r++) {
            float2 lo = unpack2(acc[r][0]);
            float2 hi = unpack2(acc[r][1]);
            float4 o;
            o.x = lrelu(lo.x + bb.x);
            o.y = lrelu(lo.y + bb.y);
            o.z = lrelu(hi.x + bb.z);
            o.w = lrelu(hi.y + bb.w);
            *(float4*)&hs[(wid * 8 + r) * D + o4] = o;
        }
    }
    __syncthreads();

    // Phase C: GEMM2 -> gmem
    wtrans(W2, Wt, stage, tid);
    gemm_core8(hs, Wt, wid, lane, acc);
    {
        int o4 = lane << 2;
        float4 bb = *(const float4*)&b2[o4];
        #pragma unroll
        for (int r = 0; r < 8; r++) {
            int rr = row0 + wid * 8 + r;
            if (rr < N) {
                float2 lo = unpack2(acc[r][0]);
                float2 hi = unpack2(acc[r][1]);
                float4 o;
                o.x = lrelu(lo.x + bb.x);
                o.y = lrelu(lo.y + bb.y);
                o.z = lrelu(hi.x + bb.z);
                o.w = lrelu(hi.y + bb.w);
                *(float4*)&out[(size_t)rr * D + o4] = o;
            }
        }
    }
}

// ---------------- launch ----------------
extern "C" void kernel_launch(void* const* d_in, const int* in_sizes, int n_in,
                              void* d_out, int out_size) {
    const float* X   = (const float*)d_in[0];
    const int*   ei  = (const int*)d_in[1];
    const float* ew  = (const float*)d_in[2];
    const float* W1  = (const float*)d_in[3];
    const float* b1  = (const float*)d_in[4];
    const float* W2  = (const float*)d_in[5];
    const float* b2  = (const float*)d_in[6];
    const float* av  = (const float*)d_in[7];
    const int*   mom = (const int*)d_in[8];

    int N = in_sizes[0] / D;
    int E = in_sizes[2];
    const int* row = ei;
    const int* col = ei + E;

    void *p_zero, *p_cx1, *p_cx2, *p_cx3, *p_cs1, *p_cs2, *p_cs3, *p_d1h, *p_d2h, *p_d3h;
    cudaGetSymbolAddress(&p_zero, g_zero3);
    cudaGetSymbolAddress(&p_cx1, g_cx1);
    cudaGetSymbolAddress(&p_cx2, g_cx2);
    cudaGetSymbolAddress(&p_cx3, g_cx3);
    cudaGetSymbolAddress(&p_cs1, g_cs1);
    cudaGetSymbolAddress(&p_cs2, g_cs2);
    cudaGetSymbolAddress(&p_cs3, g_cs3);
    cudaGetSymbolAddress(&p_d1h, g_d1h);
    cudaGetSymbolAddress(&p_d2h, g_d2h);
    cudaGetSymbolAddress(&p_d3h, g_d3h);

    cudaMemsetAsync(p_zero, 0, (3 * NMAX + 32) * sizeof(unsigned int), 0);

    int eb = (E + 255) / 256;
    int NL = N * 32;
    int xb = (NL + 255) / 256;
    int pb = (N + 3) / 4;    // pass4: 4 nodes per 64-thr block
    int mb = (N + 1) / 2;    // pass1/mid: 2 nodes per 64-thr block
    int sb = (N + 511) / 512;

    k_deg_xh<<<eb + xb, 256>>>(row, col, ew, (const float4*)X, E, NL, eb);
    k_scan12<<<sb, 512>>>(N, sb);
    k_scatter<<<eb, 256>>>(row, col, ew, E, N);

    k_pass1<<<mb, 64>>>((const float4*)X, N);   // 4th launch -> ncu capture
    k_mid<<<mb, 64>>>((const uint4*)p_cx1, (const uint4*)p_cs1,
                      (uint4*)p_cx2, (uint4*)p_cs2, (uint4*)p_d1h, N);
    k_mid<<<mb, 64>>>((const uint4*)p_cx2, (const uint4*)p_cs2,
                      (uint4*)p_cx3, (uint4*)p_cs3, (uint4*)p_d2h, N);
    k_pass4<<<pb, 64>>>((const uint4*)p_cs3, (uint4*)p_d3h, N);

    cudaFuncSetAttribute(k_epilogue, cudaFuncAttributeMaxDynamicSharedMemorySize, 98304);
    int gb = (N + 63) / 64;
    k_epilogue<<<gb, 256, 98304>>>((const float4*)X, (const float4*)av, mom,
                                   W1, b1, W2, b2, (float*)d_out, N);
}

// round 14
// speedup vs baseline: 1.0346x; 1.0346x over previous
#include <cuda_runtime.h>
#include <cuda_bf16.h>
#include <cuda_fp16.h>
#include <math.h>

#define D 128
#define NMAX 50048
#define EMAX 960000
#define SLOPE 0.01f

// ---------------- static device scratch ----------------
__device__ unsigned int g_zero3[3 * NMAX + 32];
__device__ float g_dg[NMAX];
__device__ float g_dinv[NMAX];
__device__ int   g_ptr[NMAX + 1];
__device__ int   g_bsum[1024];
__device__ uint4 g_edges[EMAX];      // {col, wG, wS, pad}
__device__ uint4 g_xh [NMAX * 16];   // X fp16: node row = 16 x uint4 (8 feats/lane)
__device__ uint4 g_cx1[NMAX * 16];   // GCN chain fp16
__device__ uint4 g_cx2[NMAX * 16];
__device__ uint4 g_cx3[NMAX * 16];
__device__ uint4 g_cs1[NMAX * 16];   // SCT chain fp16
__device__ uint4 g_cs2[NMAX * 16];
__device__ uint4 g_cs3[NMAX * 16];
__device__ uint4 g_d1h[NMAX * 16];   // fp16 SCT diffs
__device__ uint4 g_d2h[NMAX * 16];
__device__ uint4 g_d3h[NMAX * 16];

__device__ __forceinline__ float* degp() { return (float*)g_zero3; }
__device__ __forceinline__ int*   cntp() { return (int*)(g_zero3 + NMAX); }
__device__ __forceinline__ int*   curp() { return (int*)(g_zero3 + 2 * NMAX); }
__device__ __forceinline__ int*   syncp(){ return (int*)(g_zero3 + 3 * NMAX); }

// ---------------- helpers ----------------
__device__ __forceinline__ float lrelu(float v) { return v > 0.0f ? v : v * SLOPE; }
__device__ __forceinline__ float rlu(float v)   { return v > 0.0f ? v : 0.0f; }

__device__ __forceinline__ float wsum(float v) {
    #pragma unroll
    for (int o = 16; o > 0; o >>= 1) v += __shfl_xor_sync(0xffffffffu, v, o);
    return v;
}
__device__ __forceinline__ unsigned int pack_h2(float x, float y) {
    __half2 a = __floats2half2_rn(x, y);
    return *(unsigned int*)&a;
}
__device__ __forceinline__ float2 unpack_h2(unsigned int u) {
    __half2 a = *(__half2*)&u;
    return __half22float2(a);
}
__device__ __forceinline__ uint2 pack_h4u2(float4 v) {
    uint2 r;
    r.x = pack_h2(v.x, v.y);
    r.y = pack_h2(v.z, v.w);
    return r;
}
__device__ __forceinline__ float4 unpack_h4(uint2 u) {
    float2 fa = unpack_h2(u.x), fb = unpack_h2(u.y);
    return make_float4(fa.x, fa.y, fb.x, fb.y);
}
__device__ __forceinline__ unsigned long long pack2(float x, float y) {
    unsigned long long r;
    asm("mov.b64 %0, {%1, %2};" : "=l"(r) : "f"(x), "f"(y));
    return r;
}
__device__ __forceinline__ unsigned long long dup2(float x) {
    unsigned long long r;
    asm("mov.b64 %0, {%1, %1};" : "=l"(r) : "f"(x));
    return r;
}
__device__ __forceinline__ void fma2(unsigned long long &d, unsigned long long a, unsigned long long b) {
    asm("fma.rn.f32x2 %0, %1, %2, %0;" : "+l"(d) : "l"(a), "l"(b));
}
__device__ __forceinline__ float2 unpack2(unsigned long long v) {
    float2 r;
    asm("mov.b64 {%0, %1}, %2;" : "=f"(r.x), "=f"(r.y) : "l"(v));
    return r;
}
__device__ __forceinline__ void acc8f(float4 &A, float4 &B, uint4 u, float w) {
    float2 f0 = unpack_h2(u.x), f1 = unpack_h2(u.y);
    float2 f2 = unpack_h2(u.z), f3 = unpack_h2(u.w);
    A.x += w*f0.x; A.y += w*f0.y; A.z += w*f1.x; A.w += w*f1.y;
    B.x += w*f2.x; B.y += w*f2.y; B.z += w*f3.x; B.w += w*f3.y;
}

// ---------------- setup: degree atomics + X->fp16, fused (grid split) ----------------
__global__ void k_deg_xh(const int* __restrict__ row, const int* __restrict__ col,
                         const float* __restrict__ w, const float4* __restrict__ X,
                         int E, int NL, int eb) {
    int b = blockIdx.x;
    if (b < eb) {
        int e = b * 256 + threadIdx.x;
        if (e < E) {
            atomicAdd(&degp()[col[e]], w[e]);
            atomicAdd(&cntp()[row[e]], 1);
        }
    } else {
        int i = (b - eb) * 256 + threadIdx.x;
        if (i < NL) ((uint2*)g_xh)[i] = pack_h4u2(X[i]);
    }
}

// ---------------- fused 2-level scan (last-block finalize, parallel) ----------------
__global__ void k_scan12(int N, int nb) {
    __shared__ int sd[512];
    __shared__ int isLast;
    int tid = threadIdx.x;
    int i = blockIdx.x * 512 + tid;
    if (i < N) {
        float d = degp()[i];
        g_dg[i]   = rsqrtf(d + 1.0f);
        g_dinv[i] = 1.0f / d;
    }
    int v = (i < N) ? cntp()[i] : 0;
    sd[tid] = v;
    __syncthreads();
    #pragma unroll
    for (int off = 1; off < 512; off <<= 1) {
        int t = (tid >= off) ? sd[tid - off] : 0;
        __syncthreads();
        sd[tid] += t;
        __syncthreads();
    }
    if (i < N) g_ptr[i] = sd[tid] - v;
    if (tid == 511) g_bsum[blockIdx.x] = sd[511];
    __threadfence();
    if (tid == 0) {
        int old = atomicAdd(syncp(), 1);
        isLast = (old == nb - 1) ? 1 : 0;
    }
    __syncthreads();
    if (isLast) {
        int v2 = (tid < nb) ? g_bsum[tid] : 0;
        sd[tid] = v2;
        __syncthreads();
        #pragma unroll
        for (int off = 1; off < 512; off <<= 1) {
            int t = (tid >= off) ? sd[tid - off] : 0;
            __syncthreads();
            sd[tid] += t;
            __syncthreads();
        }
        if (tid < nb) g_bsum[tid] = sd[tid] - v2;
        if (tid == nb - 1) g_ptr[N] = sd[tid];
    }
}

// ---------------- finalize CSR pointers + seed scatter cursors ----------------
__global__ void k_fin(int N) {
    int i = blockIdx.x * blockDim.x + threadIdx.x;
    if (i < N) {
        int p = g_ptr[i] + g_bsum[i >> 9];
        g_ptr[i] = p;
        curp()[i] = p;
    }
}

__global__ void k_scatter(const int* __restrict__ row, const int* __restrict__ col,
                          const float* __restrict__ w, int E) {
    int e = blockIdx.x * blockDim.x + threadIdx.x;
    if (e >= E) return;
    int r = row[e], c = col[e];
    int pos = atomicAdd(&curp()[r], 1);
    float wv = w[e];
    uint4 v;
    v.x = (unsigned int)c;
    v.y = __float_as_uint(wv * g_dg[c]);
    v.z = __float_as_uint(wv * g_dinv[c]);
    v.w = 0u;
    g_edges[pos] = v;
}

// ---------------- pass 1: half-warp layout; warp serves 2 nodes; both chains (R12 proven) ----------------
__global__ __launch_bounds__(64, 12)
void k_pass1(const float4* __restrict__ X, int N) {
    int lane = threadIdx.x & 31;
    int gw = blockIdx.x * 2 + (threadIdx.x >> 5);
    int half = lane >> 4, l = lane & 15;
    int n = gw * 2 + half;
    bool act = (n < N);
    int nn = act ? n : 0;
    int s = g_ptr[nn], e = g_ptr[nn + 1];
    int mx = act ? (e - s) : 0;
    int mo = __shfl_xor_sync(0xffffffffu, mx, 16);
    if (mo > mx) mx = mo;

    float4 G0 = make_float4(0,0,0,0), G1 = make_float4(0,0,0,0);
    float4 S0 = make_float4(0,0,0,0), S1 = make_float4(0,0,0,0);
    for (int k = 0; k < mx; k += 4) {
        int i0 = s + k;
        bool v0 = act && (i0     < e);
        bool v1 = act && (i0 + 1 < e);
        bool v2 = act && (i0 + 2 < e);
        bool v3 = act && (i0 + 3 < e);
        uint4 e0 = __ldg(&g_edges[v0 ? i0     : s]);
        uint4 e1 = __ldg(&g_edges[v1 ? i0 + 1 : s]);
        uint4 e2 = __ldg(&g_edges[v2 ? i0 + 2 : s]);
        uint4 e3 = __ldg(&g_edges[v3 ? i0 + 3 : s]);
        uint4 u0 = __ldg(&g_xh[(int)e0.x * 16 + l]);
        uint4 u1 = __ldg(&g_xh[(int)e1.x * 16 + l]);
        uint4 u2 = __ldg(&g_xh[(int)e2.x * 16 + l]);
        uint4 u3 = __ldg(&g_xh[(int)e3.x * 16 + l]);
        float g0 = v0 ? __uint_as_float(e0.y) : 0.f, q0 = v0 ? __uint_as_float(e0.z) : 0.f;
        float g1 = v1 ? __uint_as_float(e1.y) : 0.f, q1 = v1 ? __uint_as_float(e1.z) : 0.f;
        float g2 = v2 ? __uint_as_float(e2.y) : 0.f, q2 = v2 ? __uint_as_float(e2.z) : 0.f;
        float g3 = v3 ? __uint_as_float(e3.y) : 0.f, q3 = v3 ? __uint_as_float(e3.z) : 0.f;
        acc8f(G0, G1, u0, g0); acc8f(S0, S1, u0, q0);
        acc8f(G0, G1, u1, g1); acc8f(S0, S1, u1, q1);
        acc8f(G0, G1, u2, g2); acc8f(S0, S1, u2, q2);
        acc8f(G0, G1, u3, g3); acc8f(S0, S1, u3, q3);
    }
    if (act) {
        float dg = g_dg[n];
        float4 x0 = X[n * 32 + 2 * l];
        float4 x1 = X[n * 32 + 2 * l + 1];
        uint4 cx, cs;
        cx.x = pack_h2((G0.x + x0.x*dg)*dg, (G0.y + x0.y*dg)*dg);
        cx.y = pack_h2((G0.z + x0.z*dg)*dg, (G0.w + x0.w*dg)*dg);
        cx.z = pack_h2((G1.x + x1.x*dg)*dg, (G1.y + x1.y*dg)*dg);
        cx.w = pack_h2((G1.z + x1.z*dg)*dg, (G1.w + x1.w*dg)*dg);
        cs.x = pack_h2(0.5f*(x0.x + S0.x), 0.5f*(x0.y + S0.y));
        cs.y = pack_h2(0.5f*(x0.z + S0.z), 0.5f*(x0.w + S0.w));
        cs.z = pack_h2(0.5f*(x1.x + S1.x), 0.5f*(x1.y + S1.y));
        cs.w = pack_h2(0.5f*(x1.z + S1.z), 0.5f*(x1.w + S1.w));
        g_cx1[n * 16 + l] = cx;
        g_cs1[n * 16 + l] = cs;
    }
}

// half-warp single-chain gather, 8-wide unroll (WSEL: 1=wG, 2=wS)
template<int WSEL>
__device__ __forceinline__ void gatherHW(const uint4* __restrict__ src, int s, int e,
                                         int l, bool act, float4 &A, float4 &B) {
    int mx = act ? (e - s) : 0;
    int mo = __shfl_xor_sync(0xffffffffu, mx, 16);
    if (mo > mx) mx = mo;
    for (int k = 0; k < mx; k += 8) {
        int i0 = s + k;
        bool vv[8];
        uint4 ee[8];
        #pragma unroll
        for (int t = 0; t < 8; t++) {
            vv[t] = act && (i0 + t < e);
            ee[t] = __ldg(&g_edges[vv[t] ? i0 + t : s]);
        }
        uint4 uu[8];
        #pragma unroll
        for (int t = 0; t < 8; t++) uu[t] = __ldg(&src[(int)ee[t].x * 16 + l]);
        #pragma unroll
        for (int t = 0; t < 8; t++) {
            float w = vv[t] ? __uint_as_float(WSEL == 1 ? ee[t].y : ee[t].z) : 0.f;
            acc8f(A, B, uu[t], w);
        }
    }
}

// ---------------- mid pass: warp0 = GCN chain (2 nodes), warp1 = SCT chain (2 nodes) ----------------
__global__ __launch_bounds__(64, 12)
void k_mid(const uint4* __restrict__ xin, const uint4* __restrict__ sin_,
           uint4* __restrict__ xout, uint4* __restrict__ sout,
           uint4* __restrict__ dout, int N) {
    int warp = threadIdx.x >> 5;
    int lane = threadIdx.x & 31;
    int half = lane >> 4, l = lane & 15;
    int n = blockIdx.x * 2 + half;
    bool act = (n < N);
    int nn = act ? n : 0;
    int s = g_ptr[nn], e = g_ptr[nn + 1];
    float4 A = make_float4(0,0,0,0), B = make_float4(0,0,0,0);

    if (warp == 0) {
        gatherHW<1>(xin, s, e, l, act, A, B);
        if (act) {
            float dg = g_dg[n];
            uint4 xg = xin[n * 16 + l];
            float2 f0 = unpack_h2(xg.x), f1 = unpack_h2(xg.y);
            float2 f2 = unpack_h2(xg.z), f3 = unpack_h2(xg.w);
            uint4 cx;
            cx.x = pack_h2((A.x + f0.x*dg)*dg, (A.y + f0.y*dg)*dg);
            cx.y = pack_h2((A.z + f1.x*dg)*dg, (A.w + f1.y*dg)*dg);
            cx.z = pack_h2((B.x + f2.x*dg)*dg, (B.y + f2.y*dg)*dg);
            cx.w = pack_h2((B.z + f3.x*dg)*dg, (B.w + f3.y*dg)*dg);
            xout[n * 16 + l] = cx;
        }
    } else {
        gatherHW<2>(sin_, s, e, l, act, A, B);
        if (act) {
            uint4 sg = sin_[n * 16 + l];
            float2 f0 = unpack_h2(sg.x), f1 = unpack_h2(sg.y);
            float2 f2 = unpack_h2(sg.z), f3 = unpack_h2(sg.w);
            uint4 cs, d;
            cs.x = pack_h2(0.5f*(f0.x + A.x), 0.5f*(f0.y + A.y));
            cs.y = pack_h2(0.5f*(f1.x + A.z), 0.5f*(f1.y + A.w));
            cs.z = pack_h2(0.5f*(f2.x + B.x), 0.5f*(f2.y + B.y));
            cs.w = pack_h2(0.5f*(f3.x + B.z), 0.5f*(f3.y + B.w));
            d.x  = pack_h2(0.5f*(f0.x - A.x), 0.5f*(f0.y - A.y));
            d.y  = pack_h2(0.5f*(f1.x - A.z), 0.5f*(f1.y - A.w));
            d.z  = pack_h2(0.5f*(f2.x - B.x), 0.5f*(f2.y - B.y));
            d.w  = pack_h2(0.5f*(f3.x - B.z), 0.5f*(f3.y - B.w));
            sout[n * 16 + l] = cs;
            dout[n * 16 + l] = d;
        }
    }
}

// ---------------- final pass: half-warp layout, gather cs3 -> d3 ----------------
__global__ __launch_bounds__(64, 12)
void k_pass4(const uint4* __restrict__ sh, uint4* __restrict__ dout, int N) {
    int lane = threadIdx.x & 31;
    int gw = blockIdx.x * 2 + (threadIdx.x >> 5);
    int half = lane >> 4, l = lane & 15;
    int n = gw * 2 + half;
    bool act = (n < N);
    int nn = act ? n : 0;
    int s = g_ptr[nn], e = g_ptr[nn + 1];
    float4 A = make_float4(0,0,0,0), B = make_float4(0,0,0,0);
    gatherHW<2>(sh, s, e, l, act, A, B);
    if (act) {
        uint4 sg = sh[n * 16 + l];
        float2 f0 = unpack_h2(sg.x), f1 = unpack_h2(sg.y);
        float2 f2 = unpack_h2(sg.z), f3 = unpack_h2(sg.w);
        uint4 d;
        d.x = pack_h2(0.5f*(f0.x - A.x), 0.5f*(f0.y - A.y));
        d.y = pack_h2(0.5f*(f1.x - A.z), 0.5f*(f1.y - A.w));
        d.z = pack_h2(0.5f*(f2.x - B.x), 0.5f*(f2.y - B.y));
        d.w = pack_h2(0.5f*(f3.x - B.z), 0.5f*(f3.y - B.w));
        dout[n * 16 + l] = d;
    }
}

// ---------------- fused epilogue: 64-row tiles, 2 blocks/SM ----------------
__device__ __forceinline__ float4 lrelu4(float4 v) {
    return make_float4(lrelu(v.x), lrelu(v.y), lrelu(v.z), lrelu(v.w));
}
__device__ __forceinline__ float apw(float d, bool is1, float mf) {
    float a = fabsf(d);
    return is1 ? a : __powf(a, mf);
}

__device__ __forceinline__ void wtrans(const float* __restrict__ W, float* Wt,
                                       float stage[32][33], int tid) {
    int tx = tid & 31, ty0 = tid >> 5;
    for (int t = 0; t < 16; t++) {
        int ko = (t >> 2) << 5, oo = (t & 3) << 5;
        #pragma unroll
        for (int i = 0; i < 4; i++) {
            int ty = ty0 + i * 8;
            stage[ty][tx] = W[(oo + ty) * D + ko + tx];
        }
        __syncthreads();
        #pragma unroll
        for (int i = 0; i < 4; i++) {
            int ty = ty0 + i * 8;
            Wt[(ko + ty) * D + oo + tx] = stage[tx][ty];
        }
        __syncthreads();
    }
}

__device__ __forceinline__ void gemm_core8(const float* hs, const float* Wt,
                                           int wid, int lane, unsigned long long acc[8][2]) {
    int o4 = lane << 2;
    #pragma unroll
    for (int r = 0; r < 8; r++) { acc[r][0] = 0ull; acc[r][1] = 0ull; }
    for (int k4 = 0; k4 < 32; k4++) {
        unsigned long long wp[4][2];
        #pragma unroll
        for (int kk = 0; kk < 4; kk++) {
            float4 wv = *(const float4*)&Wt[(k4 * 4 + kk) * D + o4];
            wp[kk][0] = pack2(wv.x, wv.y);
            wp[kk][1] = pack2(wv.z, wv.w);
        }
        #pragma unroll
        for (int r = 0; r < 8; r++) {
            float4 h4 = *(const float4*)&hs[(wid * 8 + r) * D + k4 * 4];
            unsigned long long hp;
            hp = dup2(h4.x); fma2(acc[r][0], hp, wp[0][0]); fma2(acc[r][1], hp, wp[0][1]);
            hp = dup2(h4.y); fma2(acc[r][0], hp, wp[1][0]); fma2(acc[r][1], hp, wp[1][1]);
            hp = dup2(h4.z); fma2(acc[r][0], hp, wp[2][0]); fma2(acc[r][1], hp, wp[2][1]);
            hp = dup2(h4.w); fma2(acc[r][0], hp, wp[3][0]); fma2(acc[r][1], hp, wp[3][1]);
        }
    }
}

extern __shared__ float dsm[];
__global__ __launch_bounds__(256, 2)
void k_epilogue(const float4* __restrict__ X, const float4* __restrict__ a4,
                const int* __restrict__ mom,
                const float* __restrict__ W1, const float* __restrict__ b1,
                const float* __restrict__ W2, const float* __restrict__ b2,
                float* __restrict__ out, int N) {
    float* Wt = dsm;            // 16384 floats (64KB)
    float* hs = dsm + 16384;    // 8192 floats (32KB): 64 rows x 128
    __shared__ float stage[32][33];

    int tid = threadIdx.x, wid = tid >> 5, lane = tid & 31;
    int row0 = blockIdx.x * 64;
    float4* hs4 = (float4*)hs;

    const uint2* cx1 = (const uint2*)g_cx1;
    const uint2* cx2 = (const uint2*)g_cx2;
    const uint2* cx3 = (const uint2*)g_cx3;
    const uint2* d1p = (const uint2*)g_d1h;
    const uint2* d2p = (const uint2*)g_d2h;
    const uint2* d3p = (const uint2*)g_d3h;

    float4 aX = a4[lane];
    float4 aH = a4[32 + lane];
    int mi = mom[0];
    bool is1 = (mi == 1) || (__int_as_float(mi) == 1.0f);
    float mf = 1.0f;
    if (!is1) mf = (mi > 0 && mi < 64) ? (float)mi : __int_as_float(mi);

    // Phase A: attention -> hs (8 rows per warp)
    for (int r = 0; r < 8; r++) {
        int n = row0 + wid * 8 + r;
        float4 o = make_float4(0.f, 0.f, 0.f, 0.f);
        if (n < N) {
            int base = n * 32 + lane;
            float4 xr = X[base];
            float eX = wsum(rlu(xr.x)*aX.x + rlu(xr.y)*aX.y + rlu(xr.z)*aX.z + rlu(xr.w)*aX.w);

            float4 h[6];
            h[0] = lrelu4(unpack_h4(cx1[base]));
            h[1] = lrelu4(unpack_h4(cx2[base]));
            h[2] = lrelu4(unpack_h4(cx3[base]));
            float4 d1 = unpack_h4(d1p[base]);
            float4 d2 = unpack_h4(d2p[base]);
            float4 d3 = unpack_h4(d3p[base]);
            h[3] = make_float4(apw(d1.x,is1,mf), apw(d1.y,is1,mf), apw(d1.z,is1,mf), apw(d1.w,is1,mf));
            h[4] = make_float4(apw(d2.x,is1,mf), apw(d2.y,is1,mf), apw(d2.z,is1,mf), apw(d2.w,is1,mf));
            h[5] = make_float4(apw(d3.x,is1,mf), apw(d3.y,is1,mf), apw(d3.z,is1,mf), apw(d3.w,is1,mf));

            float e[6];
            #pragma unroll
            for (int c = 0; c < 6; c++) {
                float part = rlu(h[c].x)*aH.x + rlu(h[c].y)*aH.y + rlu(h[c].z)*aH.z + rlu(h[c].w)*aH.w;
                e[c] = eX + wsum(part);
            }
            float mx = e[0];
            #pragma unroll
            for (int c = 1; c < 6; c++) mx = fmaxf(mx, e[c]);
            float at[6], s = 0.f;
            #pragma unroll
            for (int c = 0; c < 6; c++) { at[c] = __expf(e[c] - mx); s += at[c]; }
            float inv = 1.0f / (6.0f * s);
            #pragma unroll
            for (int c = 0; c < 6; c++) {
                o.x += at[c]*h[c].x; o.y += at[c]*h[c].y; o.z += at[c]*h[c].z; o.w += at[c]*h[c].w;
            }
            o.x *= inv; o.y *= inv; o.z *= inv; o.w *= inv;
        }
        hs4[(wid * 8 + r) * 32 + lane] = o;
    }
    __syncthreads();

    // Phase B: GEMM1 -> hs in place
    wtrans(W1, Wt, stage, tid);
    unsigned long long acc[8][2];
    gemm_core8(hs, Wt, wid, lane, acc);
    __syncthreads();
    {
        int o4 = lane << 2;
        float4 bb = *(const float4*)&b1[o4];
        #pragma unroll
        for (int r = 0; r < 8; r++) {
            float2 lo = unpack2(acc[r][0]);
            float2 hi = unpack2(acc[r][1]);
            float4 o;
            o.x = lrelu(lo.x + bb.x);
            o.y = lrelu(lo.y + bb.y);
            o.z = lrelu(hi.x + bb.z);
            o.w = lrelu(hi.y + bb.w);
            *(float4*)&hs[(wid * 8 + r) * D + o4] = o;
        }
    }
    __syncthreads();

    // Phase C: GEMM2 -> gmem
    wtrans(W2, Wt, stage, tid);
    gemm_core8(hs, Wt, wid, lane, acc);
    {
        int o4 = lane << 2;
        float4 bb = *(const float4*)&b2[o4];
        #pragma unroll
        for (int r = 0; r < 8; r++) {
            int rr = row0 + wid * 8 + r;
            if (rr < N) {
                float2 lo = unpack2(acc[r][0]);
                float2 hi = unpack2(acc[r][1]);
                float4 o;
                o.x = lrelu(lo.x + bb.x);
                o.y = lrelu(lo.y + bb.y);
                o.z = lrelu(hi.x + bb.z);
                o.w = lrelu(hi.y + bb.w);
                *(float4*)&out[(size_t)rr * D + o4] = o;
            }
        }
    }
}

// ---------------- launch ----------------
extern "C" void kernel_launch(void* const* d_in, const int* in_sizes, int n_in,
                              void* d_out, int out_size) {
    const float* X   = (const float*)d_in[0];
    const int*   ei  = (const int*)d_in[1];
    const float* ew  = (const float*)d_in[2];
    const float* W1  = (const float*)d_in[3];
    const float* b1  = (const float*)d_in[4];
    const float* W2  = (const float*)d_in[5];
    const float* b2  = (const float*)d_in[6];
    const float* av  = (const float*)d_in[7];
    const int*   mom = (const int*)d_in[8];

    int N = in_sizes[0] / D;
    int E = in_sizes[2];
    const int* row = ei;
    const int* col = ei + E;

    void *p_zero, *p_cx1, *p_cx2, *p_cx3, *p_cs1, *p_cs2, *p_cs3, *p_d1h, *p_d2h, *p_d3h;
    cudaGetSymbolAddress(&p_zero, g_zero3);
    cudaGetSymbolAddress(&p_cx1, g_cx1);
    cudaGetSymbolAddress(&p_cx2, g_cx2);
    cudaGetSymbolAddress(&p_cx3, g_cx3);
    cudaGetSymbolAddress(&p_cs1, g_cs1);
    cudaGetSymbolAddress(&p_cs2, g_cs2);
    cudaGetSymbolAddress(&p_cs3, g_cs3);
    cudaGetSymbolAddress(&p_d1h, g_d1h);
    cudaGetSymbolAddress(&p_d2h, g_d2h);
    cudaGetSymbolAddress(&p_d3h, g_d3h);

    cudaMemsetAsync(p_zero, 0, (3 * NMAX + 32) * sizeof(unsigned int), 0);

    int eb = (E + 255) / 256;
    int NL = N * 32;
    int xb = (NL + 255) / 256;
    int pb = (N + 3) / 4;    // pass1/pass4: 4 nodes per 64-thr block
    int mb = (N + 1) / 2;    // mid: 2 nodes per 64-thr block
    int sb = (N + 511) / 512;
    int nb = (N + 255) / 256;

    k_deg_xh<<<eb + xb, 256>>>(row, col, ew, (const float4*)X, E, NL, eb);
    k_scan12<<<sb, 512>>>(N, sb);
    k_fin<<<nb, 256>>>(N);
    k_scatter<<<eb, 256>>>(row, col, ew, E);

    k_pass1<<<pb, 64>>>((const float4*)X, N);
    k_mid<<<mb, 64>>>((const uint4*)p_cx1, (const uint4*)p_cs1,
                      (uint4*)p_cx2, (uint4*)p_cs2, (uint4*)p_d1h, N);
    k_mid<<<mb, 64>>>((const uint4*)p_cx2, (const uint4*)p_cs2,
                      (uint4*)p_cx3, (uint4*)p_cs3, (uint4*)p_d2h, N);
    k_pass4<<<pb, 64>>>((const uint4*)p_cs3, (uint4*)p_d3h, N);

    cudaFuncSetAttribute(k_epilogue, cudaFuncAttributeMaxDynamicSharedMemorySize, 98304);
    int gb = (N + 63) / 64;
    k_epilogue<<<gb, 256, 98304>>>((const float4*)X, (const float4*)av, mom,
                                   W1, b1, W2, b2, (float*)d_out, N);
}

// round 15
// speedup vs baseline: 1.0846x; 1.0484x over previous
#include <cuda_runtime.h>
#include <cuda_bf16.h>
#include <cuda_fp16.h>
#include <math.h>

#define D 128
#define NMAX 50048
#define EMAX 960000
#define SLOPE 0.01f

// ---------------- static device scratch ----------------
__device__ unsigned int g_zero3[3 * NMAX + 32];
__device__ float g_dg[NMAX];
__device__ float g_dinv[NMAX];
__device__ int   g_ptr[NMAX + 1];
__device__ int   g_bsum[1024];
__device__ float g_W1t[D * D];       // pre-transposed weights: Wt[k*D+o]
__device__ float g_W2t[D * D];
__device__ uint4 g_edges[EMAX];      // {col, wG, wS, pad}
__device__ uint4 g_xh [NMAX * 16];   // X fp16: node row = 16 x uint4 (8 feats/lane)
__device__ uint4 g_cx1[NMAX * 16];   // GCN chain fp16
__device__ uint4 g_cx2[NMAX * 16];
__device__ uint4 g_cx3[NMAX * 16];
__device__ uint4 g_cs1[NMAX * 16];   // SCT chain fp16
__device__ uint4 g_cs2[NMAX * 16];
__device__ uint4 g_cs3[NMAX * 16];
__device__ uint4 g_d1h[NMAX * 16];   // fp16 SCT diffs
__device__ uint4 g_d2h[NMAX * 16];
__device__ uint4 g_d3h[NMAX * 16];

__device__ __forceinline__ float* degp() { return (float*)g_zero3; }
__device__ __forceinline__ int*   cntp() { return (int*)(g_zero3 + NMAX); }
__device__ __forceinline__ int*   curp() { return (int*)(g_zero3 + 2 * NMAX); }
__device__ __forceinline__ int*   syncp(){ return (int*)(g_zero3 + 3 * NMAX); }

__device__ __forceinline__ int fptr(int i, int N) {
    return (i >= N) ? g_ptr[N] : (g_ptr[i] + g_bsum[i >> 9]);
}

// ---------------- helpers ----------------
__device__ __forceinline__ float lrelu(float v) { return v > 0.0f ? v : v * SLOPE; }
__device__ __forceinline__ float rlu(float v)   { return v > 0.0f ? v : 0.0f; }

__device__ __forceinline__ float wsum(float v) {
    #pragma unroll
    for (int o = 16; o > 0; o >>= 1) v += __shfl_xor_sync(0xffffffffu, v, o);
    return v;
}
__device__ __forceinline__ unsigned int pack_h2(float x, float y) {
    __half2 a = __floats2half2_rn(x, y);
    return *(unsigned int*)&a;
}
__device__ __forceinline__ float2 unpack_h2(unsigned int u) {
    __half2 a = *(__half2*)&u;
    return __half22float2(a);
}
__device__ __forceinline__ uint2 pack_h4u2(float4 v) {
    uint2 r;
    r.x = pack_h2(v.x, v.y);
    r.y = pack_h2(v.z, v.w);
    return r;
}
__device__ __forceinline__ float4 unpack_h4(uint2 u) {
    float2 fa = unpack_h2(u.x), fb = unpack_h2(u.y);
    return make_float4(fa.x, fa.y, fb.x, fb.y);
}
__device__ __forceinline__ unsigned long long pack2(float x, float y) {
    unsigned long long r;
    asm("mov.b64 %0, {%1, %2};" : "=l"(r) : "f"(x), "f"(y));
    return r;
}
__device__ __forceinline__ unsigned long long dup2(float x) {
    unsigned long long r;
    asm("mov.b64 %0, {%1, %1};" : "=l"(r) : "f"(x));
    return r;
}
__device__ __forceinline__ void fma2(unsigned long long &d, unsigned long long a, unsigned long long b) {
    asm("fma.rn.f32x2 %0, %1, %2, %0;" : "+l"(d) : "l"(a), "l"(b));
}
__device__ __forceinline__ float2 unpack2(unsigned long long v) {
    float2 r;
    asm("mov.b64 {%0, %1}, %2;" : "=f"(r.x), "=f"(r.y) : "l"(v));
    return r;
}
__device__ __forceinline__ void acc8f(float4 &A, float4 &B, uint4 u, float w) {
    float2 f0 = unpack_h2(u.x), f1 = unpack_h2(u.y);
    float2 f2 = unpack_h2(u.z), f3 = unpack_h2(u.w);
    A.x += w*f0.x; A.y += w*f0.y; A.z += w*f1.x; A.w += w*f1.y;
    B.x += w*f2.x; B.y += w*f2.y; B.z += w*f3.x; B.w += w*f3.y;
}

// ---------------- setup: degree atomics + X->fp16, fused (grid split) ----------------
__global__ void k_deg_xh(const int* __restrict__ row, const int* __restrict__ col,
                         const float* __restrict__ w, const float4* __restrict__ X,
                         int E, int NL, int eb) {
    int b = blockIdx.x;
    if (b < eb) {
        int e = b * 256 + threadIdx.x;
        if (e < E) {
            atomicAdd(&degp()[col[e]], w[e]);
            atomicAdd(&cntp()[row[e]], 1);
        }
    } else {
        int i = (b - eb) * 256 + threadIdx.x;
        if (i < NL) ((uint2*)g_xh)[i] = pack_h4u2(X[i]);
    }
}

// ---------------- fused 2-level scan (last-block finalize, parallel) ----------------
__global__ void k_scan12(int N, int nb) {
    __shared__ int sd[512];
    __shared__ int isLast;
    int tid = threadIdx.x;
    int i = blockIdx.x * 512 + tid;
    if (i < N) {
        float d = degp()[i];
        g_dg[i]   = rsqrtf(d + 1.0f);
        g_dinv[i] = 1.0f / d;
    }
    int v = (i < N) ? cntp()[i] : 0;
    sd[tid] = v;
    __syncthreads();
    #pragma unroll
    for (int off = 1; off < 512; off <<= 1) {
        int t = (tid >= off) ? sd[tid - off] : 0;
        __syncthreads();
        sd[tid] += t;
        __syncthreads();
    }
    if (i < N) g_ptr[i] = sd[tid] - v;
    if (tid == 511) g_bsum[blockIdx.x] = sd[511];
    __threadfence();
    if (tid == 0) {
        int old = atomicAdd(syncp(), 1);
        isLast = (old == nb - 1) ? 1 : 0;
    }
    __syncthreads();
    if (isLast) {
        int v2 = (tid < nb) ? g_bsum[tid] : 0;
        sd[tid] = v2;
        __syncthreads();
        #pragma unroll
        for (int off = 1; off < 512; off <<= 1) {
            int t = (tid >= off) ? sd[tid - off] : 0;
            __syncthreads();
            sd[tid] += t;
            __syncthreads();
        }
        if (tid < nb) g_bsum[tid] = sd[tid] - v2;
        if (tid == nb - 1) g_ptr[N] = sd[tid];
    }
}

__global__ void k_scatter(const int* __restrict__ row, const int* __restrict__ col,
                          const float* __restrict__ w, int E, int N) {
    int e = blockIdx.x * blockDim.x + threadIdx.x;
    if (e >= E) return;
    int r = row[e], c = col[e];
    int pos = fptr(r, N) + atomicAdd(&curp()[r], 1);
    float wv = w[e];
    uint4 v;
    v.x = (unsigned int)c;
    v.y = __float_as_uint(wv * g_dg[c]);
    v.z = __float_as_uint(wv * g_dinv[c]);
    v.w = 0u;
    g_edges[pos] = v;
}

// ---------------- weight pre-transpose (once) ----------------
__global__ void k_wt(const float* __restrict__ W1, const float* __restrict__ W2) {
    int o = blockIdx.x, k = threadIdx.x;
    g_W1t[k * D + o] = W1[o * D + k];
    g_W2t[k * D + o] = W2[o * D + k];
}

// ---------------- pass 1: half-warp layout; warp serves 2 nodes; both chains ----------------
__global__ __launch_bounds__(64, 12)
void k_pass1(const float4* __restrict__ X, int N) {
    int lane = threadIdx.x & 31;
    int gw = blockIdx.x * 2 + (threadIdx.x >> 5);
    int half = lane >> 4, l = lane & 15;
    int n = gw * 2 + half;
    bool act = (n < N);
    int nn = act ? n : 0;
    int s = fptr(nn, N), e = fptr(nn + 1, N);
    int mx = act ? (e - s) : 0;
    int mo = __shfl_xor_sync(0xffffffffu, mx, 16);
    if (mo > mx) mx = mo;

    float4 G0 = make_float4(0,0,0,0), G1 = make_float4(0,0,0,0);
    float4 S0 = make_float4(0,0,0,0), S1 = make_float4(0,0,0,0);
    for (int k = 0; k < mx; k += 4) {
        int i0 = s + k;
        bool v0 = act && (i0     < e);
        bool v1 = act && (i0 + 1 < e);
        bool v2 = act && (i0 + 2 < e);
        bool v3 = act && (i0 + 3 < e);
        uint4 e0 = __ldg(&g_edges[v0 ? i0     : s]);
        uint4 e1 = __ldg(&g_edges[v1 ? i0 + 1 : s]);
        uint4 e2 = __ldg(&g_edges[v2 ? i0 + 2 : s]);
        uint4 e3 = __ldg(&g_edges[v3 ? i0 + 3 : s]);
        uint4 u0 = __ldg(&g_xh[(int)e0.x * 16 + l]);
        uint4 u1 = __ldg(&g_xh[(int)e1.x * 16 + l]);
        uint4 u2 = __ldg(&g_xh[(int)e2.x * 16 + l]);
        uint4 u3 = __ldg(&g_xh[(int)e3.x * 16 + l]);
        float g0 = v0 ? __uint_as_float(e0.y) : 0.f, q0 = v0 ? __uint_as_float(e0.z) : 0.f;
        float g1 = v1 ? __uint_as_float(e1.y) : 0.f, q1 = v1 ? __uint_as_float(e1.z) : 0.f;
        float g2 = v2 ? __uint_as_float(e2.y) : 0.f, q2 = v2 ? __uint_as_float(e2.z) : 0.f;
        float g3 = v3 ? __uint_as_float(e3.y) : 0.f, q3 = v3 ? __uint_as_float(e3.z) : 0.f;
        acc8f(G0, G1, u0, g0); acc8f(S0, S1, u0, q0);
        acc8f(G0, G1, u1, g1); acc8f(S0, S1, u1, q1);
        acc8f(G0, G1, u2, g2); acc8f(S0, S1, u2, q2);
        acc8f(G0, G1, u3, g3); acc8f(S0, S1, u3, q3);
    }
    if (act) {
        float dg = g_dg[n];
        float4 x0 = X[n * 32 + 2 * l];
        float4 x1 = X[n * 32 + 2 * l + 1];
        uint4 cx, cs;
        cx.x = pack_h2((G0.x + x0.x*dg)*dg, (G0.y + x0.y*dg)*dg);
        cx.y = pack_h2((G0.z + x0.z*dg)*dg, (G0.w + x0.w*dg)*dg);
        cx.z = pack_h2((G1.x + x1.x*dg)*dg, (G1.y + x1.y*dg)*dg);
        cx.w = pack_h2((G1.z + x1.z*dg)*dg, (G1.w + x1.w*dg)*dg);
        cs.x = pack_h2(0.5f*(x0.x + S0.x), 0.5f*(x0.y + S0.y));
        cs.y = pack_h2(0.5f*(x0.z + S0.z), 0.5f*(x0.w + S0.w));
        cs.z = pack_h2(0.5f*(x1.x + S1.x), 0.5f*(x1.y + S1.y));
        cs.w = pack_h2(0.5f*(x1.z + S1.z), 0.5f*(x1.w + S1.w));
        g_cx1[n * 16 + l] = cx;
        g_cs1[n * 16 + l] = cs;
    }
}

// half-warp single-chain gather, 8-wide unroll (WSEL: 1=wG, 2=wS)
template<int WSEL>
__device__ __forceinline__ void gatherHW(const uint4* __restrict__ src, int s, int e,
                                         int l, bool act, float4 &A, float4 &B) {
    int mx = act ? (e - s) : 0;
    int mo = __shfl_xor_sync(0xffffffffu, mx, 16);
    if (mo > mx) mx = mo;
    for (int k = 0; k < mx; k += 8) {
        int i0 = s + k;
        bool vv[8];
        uint4 ee[8];
        #pragma unroll
        for (int t = 0; t < 8; t++) {
            vv[t] = act && (i0 + t < e);
            ee[t] = __ldg(&g_edges[vv[t] ? i0 + t : s]);
        }
        uint4 uu[8];
        #pragma unroll
        for (int t = 0; t < 8; t++) uu[t] = __ldg(&src[(int)ee[t].x * 16 + l]);
        #pragma unroll
        for (int t = 0; t < 8; t++) {
            float w = vv[t] ? __uint_as_float(WSEL == 1 ? ee[t].y : ee[t].z) : 0.f;
            acc8f(A, B, uu[t], w);
        }
    }
}

// ---------------- mid pass: warp0 = GCN chain (2 nodes), warp1 = SCT chain (2 nodes) ----------------
__global__ __launch_bounds__(64, 12)
void k_mid(const uint4* __restrict__ xin, const uint4* __restrict__ sin_,
           uint4* __restrict__ xout, uint4* __restrict__ sout,
           uint4* __restrict__ dout, int N) {
    int warp = threadIdx.x >> 5;
    int lane = threadIdx.x & 31;
    int half = lane >> 4, l = lane & 15;
    int n = blockIdx.x * 2 + half;
    bool act = (n < N);
    int nn = act ? n : 0;
    int s = fptr(nn, N), e = fptr(nn + 1, N);
    float4 A = make_float4(0,0,0,0), B = make_float4(0,0,0,0);

    if (warp == 0) {
        gatherHW<1>(xin, s, e, l, act, A, B);
        if (act) {
            float dg = g_dg[n];
            uint4 xg = xin[n * 16 + l];
            float2 f0 = unpack_h2(xg.x), f1 = unpack_h2(xg.y);
            float2 f2 = unpack_h2(xg.z), f3 = unpack_h2(xg.w);
            uint4 cx;
            cx.x = pack_h2((A.x + f0.x*dg)*dg, (A.y + f0.y*dg)*dg);
            cx.y = pack_h2((A.z + f1.x*dg)*dg, (A.w + f1.y*dg)*dg);
            cx.z = pack_h2((B.x + f2.x*dg)*dg, (B.y + f2.y*dg)*dg);
            cx.w = pack_h2((B.z + f3.x*dg)*dg, (B.w + f3.y*dg)*dg);
            xout[n * 16 + l] = cx;
        }
    } else {
        gatherHW<2>(sin_, s, e, l, act, A, B);
        if (act) {
            uint4 sg = sin_[n * 16 + l];
            float2 f0 = unpack_h2(sg.x), f1 = unpack_h2(sg.y);
            float2 f2 = unpack_h2(sg.z), f3 = unpack_h2(sg.w);
            uint4 cs, d;
            cs.x = pack_h2(0.5f*(f0.x + A.x), 0.5f*(f0.y + A.y));
            cs.y = pack_h2(0.5f*(f1.x + A.z), 0.5f*(f1.y + A.w));
            cs.z = pack_h2(0.5f*(f2.x + B.x), 0.5f*(f2.y + B.y));
            cs.w = pack_h2(0.5f*(f3.x + B.z), 0.5f*(f3.y + B.w));
            d.x  = pack_h2(0.5f*(f0.x - A.x), 0.5f*(f0.y - A.y));
            d.y  = pack_h2(0.5f*(f1.x - A.z), 0.5f*(f1.y - A.w));
            d.z  = pack_h2(0.5f*(f2.x - B.x), 0.5f*(f2.y - B.y));
            d.w  = pack_h2(0.5f*(f3.x - B.z), 0.5f*(f3.y - B.w));
            sout[n * 16 + l] = cs;
            dout[n * 16 + l] = d;
        }
    }
}

// ---------------- final pass: half-warp layout, gather cs3 -> d3 ----------------
__global__ __launch_bounds__(64, 12)
void k_pass4(const uint4* __restrict__ sh, uint4* __restrict__ dout, int N) {
    int lane = threadIdx.x & 31;
    int gw = blockIdx.x * 2 + (threadIdx.x >> 5);
    int half = lane >> 4, l = lane & 15;
    int n = gw * 2 + half;
    bool act = (n < N);
    int nn = act ? n : 0;
    int s = fptr(nn, N), e = fptr(nn + 1, N);
    float4 A = make_float4(0,0,0,0), B = make_float4(0,0,0,0);
    gatherHW<2>(sh, s, e, l, act, A, B);
    if (act) {
        uint4 sg = sh[n * 16 + l];
        float2 f0 = unpack_h2(sg.x), f1 = unpack_h2(sg.y);
        float2 f2 = unpack_h2(sg.z), f3 = unpack_h2(sg.w);
        uint4 d;
        d.x = pack_h2(0.5f*(f0.x - A.x), 0.5f*(f0.y - A.y));
        d.y = pack_h2(0.5f*(f1.x - A.z), 0.5f*(f1.y - A.w));
        d.z = pack_h2(0.5f*(f2.x - B.x), 0.5f*(f2.y - B.y));
        d.w = pack_h2(0.5f*(f3.x - B.z), 0.5f*(f3.y - B.w));
        dout[n * 16 + l] = d;
    }
}

// ---------------- fused epilogue: 64-row tiles, 2 blocks/SM, pre-transposed W ----------------
__device__ __forceinline__ float4 lrelu4(float4 v) {
    return make_float4(lrelu(v.x), lrelu(v.y), lrelu(v.z), lrelu(v.w));
}
__device__ __forceinline__ float apw(float d, bool is1, float mf) {
    float a = fabsf(d);
    return is1 ? a : __powf(a, mf);
}

__device__ __forceinline__ void gemm_core8(const float* hs, const float* Wt,
                                           int wid, int lane, unsigned long long acc[8][2]) {
    int o4 = lane << 2;
    #pragma unroll
    for (int r = 0; r < 8; r++) { acc[r][0] = 0ull; acc[r][1] = 0ull; }
    for (int k4 = 0; k4 < 32; k4++) {
        unsigned long long wp[4][2];
        #pragma unroll
        for (int kk = 0; kk < 4; kk++) {
            float4 wv = *(const float4*)&Wt[(k4 * 4 + kk) * D + o4];
            wp[kk][0] = pack2(wv.x, wv.y);
            wp[kk][1] = pack2(wv.z, wv.w);
        }
        #pragma unroll
        for (int r = 0; r < 8; r++) {
            float4 h4 = *(const float4*)&hs[(wid * 8 + r) * D + k4 * 4];
            unsigned long long hp;
            hp = dup2(h4.x); fma2(acc[r][0], hp, wp[0][0]); fma2(acc[r][1], hp, wp[0][1]);
            hp = dup2(h4.y); fma2(acc[r][0], hp, wp[1][0]); fma2(acc[r][1], hp, wp[1][1]);
            hp = dup2(h4.z); fma2(acc[r][0], hp, wp[2][0]); fma2(acc[r][1], hp, wp[2][1]);
            hp = dup2(h4.w); fma2(acc[r][0], hp, wp[3][0]); fma2(acc[r][1], hp, wp[3][1]);
        }
    }
}

extern __shared__ float dsm[];
__global__ __launch_bounds__(256, 2)
void k_epilogue(const float4* __restrict__ X, const float4* __restrict__ a4,
                const int* __restrict__ mom,
                const float* __restrict__ b1, const float* __restrict__ b2,
                float* __restrict__ out, int N) {
    float* Wt = dsm;            // 16384 floats (64KB)
    float* hs = dsm + 16384;    // 8192 floats (32KB): 64 rows x 128

    int tid = threadIdx.x, wid = tid >> 5, lane = tid & 31;
    int row0 = blockIdx.x * 64;
    float4* hs4 = (float4*)hs;
    float4* Wt4 = (float4*)Wt;

    const uint2* cx1 = (const uint2*)g_cx1;
    const uint2* cx2 = (const uint2*)g_cx2;
    const uint2* cx3 = (const uint2*)g_cx3;
    const uint2* d1p = (const uint2*)g_d1h;
    const uint2* d2p = (const uint2*)g_d2h;
    const uint2* d3p = (const uint2*)g_d3h;

    float4 aX = a4[lane];
    float4 aH = a4[32 + lane];
    int mi = mom[0];
    bool is1 = (mi == 1) || (__int_as_float(mi) == 1.0f);
    float mf = 1.0f;
    if (!is1) mf = (mi > 0 && mi < 64) ? (float)mi : __int_as_float(mi);

    // copy W1t into smem (overlaps attention phase; covered by the same barrier)
    {
        const float4* wsrc = (const float4*)g_W1t;
        #pragma unroll 4
        for (int i = tid; i < 4096; i += 256) Wt4[i] = wsrc[i];
    }

    // Phase A: attention -> hs (8 rows per warp)
    for (int r = 0; r < 8; r++) {
        int n = row0 + wid * 8 + r;
        float4 o = make_float4(0.f, 0.f, 0.f, 0.f);
        if (n < N) {
            int base = n * 32 + lane;
            float4 xr = X[base];
            float eX = wsum(rlu(xr.x)*aX.x + rlu(xr.y)*aX.y + rlu(xr.z)*aX.z + rlu(xr.w)*aX.w);

            float4 h[6];
            h[0] = lrelu4(unpack_h4(cx1[base]));
            h[1] = lrelu4(unpack_h4(cx2[base]));
            h[2] = lrelu4(unpack_h4(cx3[base]));
            float4 d1 = unpack_h4(d1p[base]);
            float4 d2 = unpack_h4(d2p[base]);
            float4 d3 = unpack_h4(d3p[base]);
            h[3] = make_float4(apw(d1.x,is1,mf), apw(d1.y,is1,mf), apw(d1.z,is1,mf), apw(d1.w,is1,mf));
            h[4] = make_float4(apw(d2.x,is1,mf), apw(d2.y,is1,mf), apw(d2.z,is1,mf), apw(d2.w,is1,mf));
            h[5] = make_float4(apw(d3.x,is1,mf), apw(d3.y,is1,mf), apw(d3.z,is1,mf), apw(d3.w,is1,mf));

            float e[6];
            #pragma unroll
            for (int c = 0; c < 6; c++) {
                float part = rlu(h[c].x)*aH.x + rlu(h[c].y)*aH.y + rlu(h[c].z)*aH.z + rlu(h[c].w)*aH.w;
                e[c] = eX + wsum(part);
            }
            float mx = e[0];
            #pragma unroll
            for (int c = 1; c < 6; c++) mx = fmaxf(mx, e[c]);
            float at[6], s = 0.f;
            #pragma unroll
            for (int c = 0; c < 6; c++) { at[c] = __expf(e[c] - mx); s += at[c]; }
            float inv = 1.0f / (6.0f * s);
            #pragma unroll
            for (int c = 0; c < 6; c++) {
                o.x += at[c]*h[c].x; o.y += at[c]*h[c].y; o.z += at[c]*h[c].z; o.w += at[c]*h[c].w;
            }
            o.x *= inv; o.y *= inv; o.z *= inv; o.w *= inv;
        }
        hs4[(wid * 8 + r) * 32 + lane] = o;
    }
    __syncthreads();

    // Phase B: GEMM1 -> hs in place
    unsigned long long acc[8][2];
    gemm_core8(hs, Wt, wid, lane, acc);
    __syncthreads();   // all Wt/hs reads done
    // copy W2t into smem (overlaps activation writeback)
    {
        const float4* wsrc = (const float4*)g_W2t;
        #pragma unroll 4
        for (int i = tid; i < 4096; i += 256) Wt4[i] = wsrc[i];
    }
    {
        int o4 = lane << 2;
        float4 bb = *(const float4*)&b1[o4];
        #pragma unroll
        for (int r = 0; r < 8; r++) {
            float2 lo = unpack2(acc[r][0]);
            float2 hi = unpack2(acc[r][1]);
            float4 o;
            o.x = lrelu(lo.x + bb.x);
            o.y = lrelu(lo.y + bb.y);
            o.z = lrelu(hi.x + bb.z);
            o.w = lrelu(hi.y + bb.w);
            *(float4*)&hs[(wid * 8 + r) * D + o4] = o;
        }
    }
    __syncthreads();

    // Phase C: GEMM2 -> gmem
    gemm_core8(hs, Wt, wid, lane, acc);
    {
        int o4 = lane << 2;
        float4 bb = *(const float4*)&b2[o4];
        #pragma unroll
        for (int r = 0; r < 8; r++) {
            int rr = row0 + wid * 8 + r;
            if (rr < N) {
                float2 lo = unpack2(acc[r][0]);
                float2 hi = unpack2(acc[r][1]);
                float4 o;
                o.x = lrelu(lo.x + bb.x);
                o.y = lrelu(lo.y + bb.y);
                o.z = lrelu(hi.x + bb.z);
                o.w = lrelu(hi.y + bb.w);
                *(float4*)&out[(size_t)rr * D + o4] = o;
            }
        }
    }
}

// ---------------- launch ----------------
extern "C" void kernel_launch(void* const* d_in, const int* in_sizes, int n_in,
                              void* d_out, int out_size) {
    const float* X   = (const float*)d_in[0];
    const int*   ei  = (const int*)d_in[1];
    const float* ew  = (const float*)d_in[2];
    const float* W1  = (const float*)d_in[3];
    const float* b1  = (const float*)d_in[4];
    const float* W2  = (const float*)d_in[5];
    const float* b2  = (const float*)d_in[6];
    const float* av  = (const float*)d_in[7];
    const int*   mom = (const int*)d_in[8];

    int N = in_sizes[0] / D;
    int E = in_sizes[2];
    const int* row = ei;
    const int* col = ei + E;

    void *p_zero, *p_cx1, *p_cx2, *p_cx3, *p_cs1, *p_cs2, *p_cs3, *p_d1h, *p_d2h, *p_d3h;
    cudaGetSymbolAddress(&p_zero, g_zero3);
    cudaGetSymbolAddress(&p_cx1, g_cx1);
    cudaGetSymbolAddress(&p_cx2, g_cx2);
    cudaGetSymbolAddress(&p_cx3, g_cx3);
    cudaGetSymbolAddress(&p_cs1, g_cs1);
    cudaGetSymbolAddress(&p_cs2, g_cs2);
    cudaGetSymbolAddress(&p_cs3, g_cs3);
    cudaGetSymbolAddress(&p_d1h, g_d1h);
    cudaGetSymbolAddress(&p_d2h, g_d2h);
    cudaGetSymbolAddress(&p_d3h, g_d3h);

    cudaMemsetAsync(p_zero, 0, (3 * NMAX + 32) * sizeof(unsigned int), 0);

    int eb = (E + 255) / 256;
    int NL = N * 32;
    int xb = (NL + 255) / 256;
    int pb = (N + 3) / 4;    // pass1/pass4: 4 nodes per 64-thr block
    int mb = (N + 1) / 2;    // mid: 2 nodes per 64-thr block
    int sb = (N + 511) / 512;

    k_deg_xh<<<eb + xb, 256>>>(row, col, ew, (const float4*)X, E, NL, eb);
    k_scan12<<<sb, 512>>>(N, sb);
    k_scatter<<<eb, 256>>>(row, col, ew, E, N);

    k_pass1<<<pb, 64>>>((const float4*)X, N);   // 4th launch -> ncu capture
    k_mid<<<mb, 64>>>((const uint4*)p_cx1, (const uint4*)p_cs1,
                      (uint4*)p_cx2, (uint4*)p_cs2, (uint4*)p_d1h, N);
    k_mid<<<mb, 64>>>((const uint4*)p_cx2, (const uint4*)p_cs2,
                      (uint4*)p_cx3, (uint4*)p_cs3, (uint4*)p_d2h, N);
    k_pass4<<<pb, 64>>>((const uint4*)p_cs3, (uint4*)p_d3h, N);
    k_wt<<<D, D>>>(W1, W2);

    cudaFuncSetAttribute(k_epilogue, cudaFuncAttributeMaxDynamicSharedMemorySize, 98304);
    int gb = (N + 63) / 64;
    k_epilogue<<<gb, 256, 98304>>>((const float4*)X, (const float4*)av, mom,
                                   b1, b2, (float*)d_out, N);
}

// round 16
// speedup vs baseline: 1.1210x; 1.0335x over previous
#include <cuda_runtime.h>
#include <cuda_bf16.h>
#include <cuda_fp16.h>
#include <math.h>

#define D 128
#define NMAX 50048
#define EMAX 960000
#define SLOPE 0.01f

// ---------------- static device scratch ----------------
__device__ unsigned int g_zero3[3 * NMAX + 32];
__device__ float g_dg[NMAX];
__device__ float g_dinv[NMAX];
__device__ int   g_ptr[NMAX + 1];
__device__ int   g_bsum[1024];
__device__ __half g_W1h[D * D];      // pre-transposed fp16 weights: Wt[k*D+o]
__device__ __half g_W2h[D * D];
__device__ uint4 g_edges[EMAX];      // {col, wG, wS, pad}
__device__ uint4 g_xh [NMAX * 16];   // X fp16: node row = 16 x uint4 (8 feats/lane)
__device__ uint4 g_cx1[NMAX * 16];   // GCN chain fp16
__device__ uint4 g_cx2[NMAX * 16];
__device__ uint4 g_cx3[NMAX * 16];
__device__ uint4 g_cs1[NMAX * 16];   // SCT chain fp16
__device__ uint4 g_cs2[NMAX * 16];
__device__ uint4 g_cs3[NMAX * 16];
__device__ uint4 g_d1h[NMAX * 16];   // fp16 SCT diffs
__device__ uint4 g_d2h[NMAX * 16];
__device__ uint4 g_d3h[NMAX * 16];

__device__ __forceinline__ float* degp() { return (float*)g_zero3; }
__device__ __forceinline__ int*   cntp() { return (int*)(g_zero3 + NMAX); }
__device__ __forceinline__ int*   curp() { return (int*)(g_zero3 + 2 * NMAX); }
__device__ __forceinline__ int*   syncp(){ return (int*)(g_zero3 + 3 * NMAX); }

__device__ __forceinline__ int fptr(int i, int N) {
    return (i >= N) ? g_ptr[N] : (g_ptr[i] + g_bsum[i >> 9]);
}

// ---------------- helpers ----------------
__device__ __forceinline__ float lrelu(float v) { return v > 0.0f ? v : v * SLOPE; }
__device__ __forceinline__ float rlu(float v)   { return v > 0.0f ? v : 0.0f; }

__device__ __forceinline__ float wsum(float v) {
    #pragma unroll
    for (int o = 16; o > 0; o >>= 1) v += __shfl_xor_sync(0xffffffffu, v, o);
    return v;
}
__device__ __forceinline__ unsigned int pack_h2(float x, float y) {
    __half2 a = __floats2half2_rn(x, y);
    return *(unsigned int*)&a;
}
__device__ __forceinline__ float2 unpack_h2(unsigned int u) {
    __half2 a = *(__half2*)&u;
    return __half22float2(a);
}
__device__ __forceinline__ uint2 pack_h4u2(float4 v) {
    uint2 r;
    r.x = pack_h2(v.x, v.y);
    r.y = pack_h2(v.z, v.w);
    return r;
}
__device__ __forceinline__ float4 unpack_h4(uint2 u) {
    float2 fa = unpack_h2(u.x), fb = unpack_h2(u.y);
    return make_float4(fa.x, fa.y, fb.x, fb.y);
}
__device__ __forceinline__ unsigned long long pack2(float x, float y) {
    unsigned long long r;
    asm("mov.b64 %0, {%1, %2};" : "=l"(r) : "f"(x), "f"(y));
    return r;
}
__device__ __forceinline__ unsigned long long dup2(float x) {
    unsigned long long r;
    asm("mov.b64 %0, {%1, %1};" : "=l"(r) : "f"(x));
    return r;
}
__device__ __forceinline__ void fma2(unsigned long long &d, unsigned long long a, unsigned long long b) {
    asm("fma.rn.f32x2 %0, %1, %2, %0;" : "+l"(d) : "l"(a), "l"(b));
}
__device__ __forceinline__ float2 unpack2(unsigned long long v) {
    float2 r;
    asm("mov.b64 {%0, %1}, %2;" : "=f"(r.x), "=f"(r.y) : "l"(v));
    return r;
}
__device__ __forceinline__ void acc8f(float4 &A, float4 &B, uint4 u, float w) {
    float2 f0 = unpack_h2(u.x), f1 = unpack_h2(u.y);
    float2 f2 = unpack_h2(u.z), f3 = unpack_h2(u.w);
    A.x += w*f0.x; A.y += w*f0.y; A.z += w*f1.x; A.w += w*f1.y;
    B.x += w*f2.x; B.y += w*f2.y; B.z += w*f3.x; B.w += w*f3.y;
}

// ---------------- setup: degree atomics + X->fp16, fused (grid split) ----------------
__global__ void k_deg_xh(const int* __restrict__ row, const int* __restrict__ col,
                         const float* __restrict__ w, const float4* __restrict__ X,
                         int E, int NL, int eb) {
    int b = blockIdx.x;
    if (b < eb) {
        int e = b * 256 + threadIdx.x;
        if (e < E) {
            atomicAdd(&degp()[col[e]], w[e]);
            atomicAdd(&cntp()[row[e]], 1);
        }
    } else {
        int i = (b - eb) * 256 + threadIdx.x;
        if (i < NL) ((uint2*)g_xh)[i] = pack_h4u2(X[i]);
    }
}

// ---------------- fused 2-level scan (last-block finalize, parallel) ----------------
__global__ void k_scan12(int N, int nb) {
    __shared__ int sd[512];
    __shared__ int isLast;
    int tid = threadIdx.x;
    int i = blockIdx.x * 512 + tid;
    if (i < N) {
        float d = degp()[i];
        g_dg[i]   = rsqrtf(d + 1.0f);
        g_dinv[i] = 1.0f / d;
    }
    int v = (i < N) ? cntp()[i] : 0;
    sd[tid] = v;
    __syncthreads();
    #pragma unroll
    for (int off = 1; off < 512; off <<= 1) {
        int t = (tid >= off) ? sd[tid - off] : 0;
        __syncthreads();
        sd[tid] += t;
        __syncthreads();
    }
    if (i < N) g_ptr[i] = sd[tid] - v;
    if (tid == 511) g_bsum[blockIdx.x] = sd[511];
    __threadfence();
    if (tid == 0) {
        int old = atomicAdd(syncp(), 1);
        isLast = (old == nb - 1) ? 1 : 0;
    }
    __syncthreads();
    if (isLast) {
        int v2 = (tid < nb) ? g_bsum[tid] : 0;
        sd[tid] = v2;
        __syncthreads();
        #pragma unroll
        for (int off = 1; off < 512; off <<= 1) {
            int t = (tid >= off) ? sd[tid - off] : 0;
            __syncthreads();
            sd[tid] += t;
            __syncthreads();
        }
        if (tid < nb) g_bsum[tid] = sd[tid] - v2;
        if (tid == nb - 1) g_ptr[N] = sd[tid];
    }
}

__global__ void k_scatter(const int* __restrict__ row, const int* __restrict__ col,
                          const float* __restrict__ w, int E, int N) {
    int e = blockIdx.x * blockDim.x + threadIdx.x;
    if (e >= E) return;
    int r = row[e], c = col[e];
    int pos = fptr(r, N) + atomicAdd(&curp()[r], 1);
    float wv = w[e];
    uint4 v;
    v.x = (unsigned int)c;
    v.y = __float_as_uint(wv * g_dg[c]);
    v.z = __float_as_uint(wv * g_dinv[c]);
    v.w = 0u;
    g_edges[pos] = v;
}

// ---------------- weight pre-transpose to fp16 (once) ----------------
__global__ void k_wt(const float* __restrict__ W1, const float* __restrict__ W2) {
    int o = blockIdx.x, k = threadIdx.x;
    g_W1h[k * D + o] = __float2half_rn(W1[o * D + k]);
    g_W2h[k * D + o] = __float2half_rn(W2[o * D + k]);
}

// ---------------- pass 1: half-warp layout; warp serves 2 nodes; both chains ----------------
__global__ __launch_bounds__(64, 12)
void k_pass1(const float4* __restrict__ X, int N) {
    int lane = threadIdx.x & 31;
    int gw = blockIdx.x * 2 + (threadIdx.x >> 5);
    int half = lane >> 4, l = lane & 15;
    int n = gw * 2 + half;
    bool act = (n < N);
    int nn = act ? n : 0;
    int s = fptr(nn, N), e = fptr(nn + 1, N);
    int mx = act ? (e - s) : 0;
    int mo = __shfl_xor_sync(0xffffffffu, mx, 16);
    if (mo > mx) mx = mo;

    float4 G0 = make_float4(0,0,0,0), G1 = make_float4(0,0,0,0);
    float4 S0 = make_float4(0,0,0,0), S1 = make_float4(0,0,0,0);
    for (int k = 0; k < mx; k += 4) {
        int i0 = s + k;
        bool v0 = act && (i0     < e);
        bool v1 = act && (i0 + 1 < e);
        bool v2 = act && (i0 + 2 < e);
        bool v3 = act && (i0 + 3 < e);
        uint4 e0 = __ldg(&g_edges[v0 ? i0     : s]);
        uint4 e1 = __ldg(&g_edges[v1 ? i0 + 1 : s]);
        uint4 e2 = __ldg(&g_edges[v2 ? i0 + 2 : s]);
        uint4 e3 = __ldg(&g_edges[v3 ? i0 + 3 : s]);
        uint4 u0 = __ldg(&g_xh[(int)e0.x * 16 + l]);
        uint4 u1 = __ldg(&g_xh[(int)e1.x * 16 + l]);
        uint4 u2 = __ldg(&g_xh[(int)e2.x * 16 + l]);
        uint4 u3 = __ldg(&g_xh[(int)e3.x * 16 + l]);
        float g0 = v0 ? __uint_as_float(e0.y) : 0.f, q0 = v0 ? __uint_as_float(e0.z) : 0.f;
        float g1 = v1 ? __uint_as_float(e1.y) : 0.f, q1 = v1 ? __uint_as_float(e1.z) : 0.f;
        float g2 = v2 ? __uint_as_float(e2.y) : 0.f, q2 = v2 ? __uint_as_float(e2.z) : 0.f;
        float g3 = v3 ? __uint_as_float(e3.y) : 0.f, q3 = v3 ? __uint_as_float(e3.z) : 0.f;
        acc8f(G0, G1, u0, g0); acc8f(S0, S1, u0, q0);
        acc8f(G0, G1, u1, g1); acc8f(S0, S1, u1, q1);
        acc8f(G0, G1, u2, g2); acc8f(S0, S1, u2, q2);
        acc8f(G0, G1, u3, g3); acc8f(S0, S1, u3, q3);
    }
    if (act) {
        float dg = g_dg[n];
        float4 x0 = X[n * 32 + 2 * l];
        float4 x1 = X[n * 32 + 2 * l + 1];
        uint4 cx, cs;
        cx.x = pack_h2((G0.x + x0.x*dg)*dg, (G0.y + x0.y*dg)*dg);
        cx.y = pack_h2((G0.z + x0.z*dg)*dg, (G0.w + x0.w*dg)*dg);
        cx.z = pack_h2((G1.x + x1.x*dg)*dg, (G1.y + x1.y*dg)*dg);
        cx.w = pack_h2((G1.z + x1.z*dg)*dg, (G1.w + x1.w*dg)*dg);
        cs.x = pack_h2(0.5f*(x0.x + S0.x), 0.5f*(x0.y + S0.y));
        cs.y = pack_h2(0.5f*(x0.z + S0.z), 0.5f*(x0.w + S0.w));
        cs.z = pack_h2(0.5f*(x1.x + S1.x), 0.5f*(x1.y + S1.y));
        cs.w = pack_h2(0.5f*(x1.z + S1.z), 0.5f*(x1.w + S1.w));
        g_cx1[n * 16 + l] = cx;
        g_cs1[n * 16 + l] = cs;
    }
}

// half-warp single-chain gather, 8-wide unroll (WSEL: 1=wG, 2=wS)
template<int WSEL>
__device__ __forceinline__ void gatherHW(const uint4* __restrict__ src, int s, int e,
                                         int l, bool act, float4 &A, float4 &B) {
    int mx = act ? (e - s) : 0;
    int mo = __shfl_xor_sync(0xffffffffu, mx, 16);
    if (mo > mx) mx = mo;
    for (int k = 0; k < mx; k += 8) {
        int i0 = s + k;
        bool vv[8];
        uint4 ee[8];
        #pragma unroll
        for (int t = 0; t < 8; t++) {
            vv[t] = act && (i0 + t < e);
            ee[t] = __ldg(&g_edges[vv[t] ? i0 + t : s]);
        }
        uint4 uu[8];
        #pragma unroll
        for (int t = 0; t < 8; t++) uu[t] = __ldg(&src[(int)ee[t].x * 16 + l]);
        #pragma unroll
        for (int t = 0; t < 8; t++) {
            float w = vv[t] ? __uint_as_float(WSEL == 1 ? ee[t].y : ee[t].z) : 0.f;
            acc8f(A, B, uu[t], w);
        }
    }
}

// ---------------- mid pass: warp0 = GCN chain (2 nodes), warp1 = SCT chain (2 nodes) ----------------
__global__ __launch_bounds__(64, 12)
void k_mid(const uint4* __restrict__ xin, const uint4* __restrict__ sin_,
           uint4* __restrict__ xout, uint4* __restrict__ sout,
           uint4* __restrict__ dout, int N) {
    int warp = threadIdx.x >> 5;
    int lane = threadIdx.x & 31;
    int half = lane >> 4, l = lane & 15;
    int n = blockIdx.x * 2 + half;
    bool act = (n < N);
    int nn = act ? n : 0;
    int s = fptr(nn, N), e = fptr(nn + 1, N);
    float4 A = make_float4(0,0,0,0), B = make_float4(0,0,0,0);

    if (warp == 0) {
        gatherHW<1>(xin, s, e, l, act, A, B);
        if (act) {
            float dg = g_dg[n];
            uint4 xg = xin[n * 16 + l];
            float2 f0 = unpack_h2(xg.x), f1 = unpack_h2(xg.y);
            float2 f2 = unpack_h2(xg.z), f3 = unpack_h2(xg.w);
            uint4 cx;
            cx.x = pack_h2((A.x + f0.x*dg)*dg, (A.y + f0.y*dg)*dg);
            cx.y = pack_h2((A.z + f1.x*dg)*dg, (A.w + f1.y*dg)*dg);
            cx.z = pack_h2((B.x + f2.x*dg)*dg, (B.y + f2.y*dg)*dg);
            cx.w = pack_h2((B.z + f3.x*dg)*dg, (B.w + f3.y*dg)*dg);
            xout[n * 16 + l] = cx;
        }
    } else {
        gatherHW<2>(sin_, s, e, l, act, A, B);
        if (act) {
            uint4 sg = sin_[n * 16 + l];
            float2 f0 = unpack_h2(sg.x), f1 = unpack_h2(sg.y);
            float2 f2 = unpack_h2(sg.z), f3 = unpack_h2(sg.w);
            uint4 cs, d;
            cs.x = pack_h2(0.5f*(f0.x + A.x), 0.5f*(f0.y + A.y));
            cs.y = pack_h2(0.5f*(f1.x + A.z), 0.5f*(f1.y + A.w));
            cs.z = pack_h2(0.5f*(f2.x + B.x), 0.5f*(f2.y + B.y));
            cs.w = pack_h2(0.5f*(f3.x + B.z), 0.5f*(f3.y + B.w));
            d.x  = pack_h2(0.5f*(f0.x - A.x), 0.5f*(f0.y - A.y));
            d.y  = pack_h2(0.5f*(f1.x - A.z), 0.5f*(f1.y - A.w));
            d.z  = pack_h2(0.5f*(f2.x - B.x), 0.5f*(f2.y - B.y));
            d.w  = pack_h2(0.5f*(f3.x - B.z), 0.5f*(f3.y - B.w));
            sout[n * 16 + l] = cs;
            dout[n * 16 + l] = d;
        }
    }
}

// ---------------- final pass: half-warp layout, gather cs3 -> d3 ----------------
__global__ __launch_bounds__(64, 12)
void k_pass4(const uint4* __restrict__ sh, uint4* __restrict__ dout, int N) {
    int lane = threadIdx.x & 31;
    int gw = blockIdx.x * 2 + (threadIdx.x >> 5);
    int half = lane >> 4, l = lane & 15;
    int n = gw * 2 + half;
    bool act = (n < N);
    int nn = act ? n : 0;
    int s = fptr(nn, N), e = fptr(nn + 1, N);
    float4 A = make_float4(0,0,0,0), B = make_float4(0,0,0,0);
    gatherHW<2>(sh, s, e, l, act, A, B);
    if (act) {
        uint4 sg = sh[n * 16 + l];
        float2 f0 = unpack_h2(sg.x), f1 = unpack_h2(sg.y);
        float2 f2 = unpack_h2(sg.z), f3 = unpack_h2(sg.w);
        uint4 d;
        d.x = pack_h2(0.5f*(f0.x - A.x), 0.5f*(f0.y - A.y));
        d.y = pack_h2(0.5f*(f1.x - A.z), 0.5f*(f1.y - A.w));
        d.z = pack_h2(0.5f*(f2.x - B.x), 0.5f*(f2.y - B.y));
        d.w = pack_h2(0.5f*(f3.x - B.z), 0.5f*(f3.y - B.w));
        dout[n * 16 + l] = d;
    }
}

// ---------------- fused epilogue: 64-row tiles, 3 blocks/SM, fp16 smem weights ----------------
__device__ __forceinline__ float4 lrelu4(float4 v) {
    return make_float4(lrelu(v.x), lrelu(v.y), lrelu(v.z), lrelu(v.w));
}
__device__ __forceinline__ float apw(float d, bool is1, float mf) {
    float a = fabsf(d);
    return is1 ? a : __powf(a, mf);
}

__device__ __forceinline__ void gemm_core8h(const float* hs, const unsigned int* Wth,
                                            int wid, int lane, unsigned long long acc[8][2]) {
    int o4 = lane << 2;                 // output index (halves)
    #pragma unroll
    for (int r = 0; r < 8; r++) { acc[r][0] = 0ull; acc[r][1] = 0ull; }
    for (int k4 = 0; k4 < 32; k4++) {
        unsigned long long wp[4][2];
        #pragma unroll
        for (int kk = 0; kk < 4; kk++) {
            // row (k4*4+kk) has D halves; lane reads halves [o4..o4+3] = 2 uint32
            uint2 hw = *(const uint2*)&Wth[((k4 * 4 + kk) * D + o4) >> 1];
            float2 fa = unpack_h2(hw.x);
            float2 fb = unpack_h2(hw.y);
            wp[kk][0] = pack2(fa.x, fa.y);
            wp[kk][1] = pack2(fb.x, fb.y);
        }
        #pragma unroll
        for (int r = 0; r < 8; r++) {
            float4 h4 = *(const float4*)&hs[(wid * 8 + r) * D + k4 * 4];
            unsigned long long hp;
            hp = dup2(h4.x); fma2(acc[r][0], hp, wp[0][0]); fma2(acc[r][1], hp, wp[0][1]);
            hp = dup2(h4.y); fma2(acc[r][0], hp, wp[1][0]); fma2(acc[r][1], hp, wp[1][1]);
            hp = dup2(h4.z); fma2(acc[r][0], hp, wp[2][0]); fma2(acc[r][1], hp, wp[2][1]);
            hp = dup2(h4.w); fma2(acc[r][0], hp, wp[3][0]); fma2(acc[r][1], hp, wp[3][1]);
        }
    }
}

extern __shared__ float dsm[];
__global__ __launch_bounds__(256, 3)
void k_epilogue(const float4* __restrict__ X, const float4* __restrict__ a4,
                const int* __restrict__ mom,
                const float* __restrict__ b1, const float* __restrict__ b2,
                float* __restrict__ out, int N) {
    unsigned int* Wth = (unsigned int*)dsm;   // 8192 u32 = 16384 halves (32KB)
    float* hs = dsm + 8192;                   // 8192 floats (32KB): 64 rows x 128

    int tid = threadIdx.x, wid = tid >> 5, lane = tid & 31;
    int row0 = blockIdx.x * 64;
    float4* hs4 = (float4*)hs;
    uint4* Wth4 = (uint4*)Wth;

    const uint2* cx1 = (const uint2*)g_cx1;
    const uint2* cx2 = (const uint2*)g_cx2;
    const uint2* cx3 = (const uint2*)g_cx3;
    const uint2* d1p = (const uint2*)g_d1h;
    const uint2* d2p = (const uint2*)g_d2h;
    const uint2* d3p = (const uint2*)g_d3h;

    float4 aX = a4[lane];
    float4 aH = a4[32 + lane];
    int mi = mom[0];
    bool is1 = (mi == 1) || (__int_as_float(mi) == 1.0f);
    float mf = 1.0f;
    if (!is1) mf = (mi > 0 && mi < 64) ? (float)mi : __int_as_float(mi);

    // copy W1h into smem (overlaps attention phase; covered by the same barrier)
    {
        const uint4* wsrc = (const uint4*)g_W1h;
        #pragma unroll 4
        for (int i = tid; i < 2048; i += 256) Wth4[i] = wsrc[i];
    }

    // Phase A: attention -> hs (8 rows per warp)
    for (int r = 0; r < 8; r++) {
        int n = row0 + wid * 8 + r;
        float4 o = make_float4(0.f, 0.f, 0.f, 0.f);
        if (n < N) {
            int base = n * 32 + lane;
            float4 xr = X[base];
            float eX = wsum(rlu(xr.x)*aX.x + rlu(xr.y)*aX.y + rlu(xr.z)*aX.z + rlu(xr.w)*aX.w);

            float4 h[6];
            h[0] = lrelu4(unpack_h4(cx1[base]));
            h[1] = lrelu4(unpack_h4(cx2[base]));
            h[2] = lrelu4(unpack_h4(cx3[base]));
            float4 d1 = unpack_h4(d1p[base]);
            float4 d2 = unpack_h4(d2p[base]);
            float4 d3 = unpack_h4(d3p[base]);
            h[3] = make_float4(apw(d1.x,is1,mf), apw(d1.y,is1,mf), apw(d1.z,is1,mf), apw(d1.w,is1,mf));
            h[4] = make_float4(apw(d2.x,is1,mf), apw(d2.y,is1,mf), apw(d2.z,is1,mf), apw(d2.w,is1,mf));
            h[5] = make_float4(apw(d3.x,is1,mf), apw(d3.y,is1,mf), apw(d3.z,is1,mf), apw(d3.w,is1,mf));

            float e[6];
            #pragma unroll
            for (int c = 0; c < 6; c++) {
                float part = rlu(h[c].x)*aH.x + rlu(h[c].y)*aH.y + rlu(h[c].z)*aH.z + rlu(h[c].w)*aH.w;
                e[c] = eX + wsum(part);
            }
            float mx = e[0];
            #pragma unroll
            for (int c = 1; c < 6; c++) mx = fmaxf(mx, e[c]);
            float at[6], s = 0.f;
            #pragma unroll
            for (int c = 0; c < 6; c++) { at[c] = __expf(e[c] - mx); s += at[c]; }
            float inv = 1.0f / (6.0f * s);
            #pragma unroll
            for (int c = 0; c < 6; c++) {
                o.x += at[c]*h[c].x; o.y += at[c]*h[c].y; o.z += at[c]*h[c].z; o.w += at[c]*h[c].w;
            }
            o.x *= inv; o.y *= inv; o.z *= inv; o.w *= inv;
        }
        hs4[(wid * 8 + r) * 32 + lane] = o;
    }
    __syncthreads();

    // Phase B: GEMM1 -> hs in place
    unsigned long long acc[8][2];
    gemm_core8h(hs, Wth, wid, lane, acc);
    __syncthreads();   // all Wth/hs reads done
    // copy W2h into smem (overlaps activation writeback)
    {
        const uint4* wsrc = (const uint4*)g_W2h;
        #pragma unroll 4
        for (int i = tid; i < 2048; i += 256) Wth4[i] = wsrc[i];
    }
    {
        int o4 = lane << 2;
        float4 bb = *(const float4*)&b1[o4];
        #pragma unroll
        for (int r = 0; r < 8; r++) {
            float2 lo = unpack2(acc[r][0]);
            float2 hi = unpack2(acc[r][1]);
            float4 o;
            o.x = lrelu(lo.x + bb.x);
            o.y = lrelu(lo.y + bb.y);
            o.z = lrelu(hi.x + bb.z);
            o.w = lrelu(hi.y + bb.w);
            *(float4*)&hs[(wid * 8 + r) * D + o4] = o;
        }
    }
    __syncthreads();

    // Phase C: GEMM2 -> gmem
    gemm_core8h(hs, Wth, wid, lane, acc);
    {
        int o4 = lane << 2;
        float4 bb = *(const float4*)&b2[o4];
        #pragma unroll
        for (int r = 0; r < 8; r++) {
            int rr = row0 + wid * 8 + r;
            if (rr < N) {
                float2 lo = unpack2(acc[r][0]);
                float2 hi = unpack2(acc[r][1]);
                float4 o;
                o.x = lrelu(lo.x + bb.x);
                o.y = lrelu(lo.y + bb.y);
                o.z = lrelu(hi.x + bb.z);
                o.w = lrelu(hi.y + bb.w);
                *(float4*)&out[(size_t)rr * D + o4] = o;
            }
        }
    }
}

// ---------------- launch ----------------
extern "C" void kernel_launch(void* const* d_in, const int* in_sizes, int n_in,
                              void* d_out, int out_size) {
    const float* X   = (const float*)d_in[0];
    const int*   ei  = (const int*)d_in[1];
    const float* ew  = (const float*)d_in[2];
    const float* W1  = (const float*)d_in[3];
    const float* b1  = (const float*)d_in[4];
    const float* W2  = (const float*)d_in[5];
    const float* b2  = (const float*)d_in[6];
    const float* av  = (const float*)d_in[7];
    const int*   mom = (const int*)d_in[8];

    int N = in_sizes[0] / D;
    int E = in_sizes[2];
    const int* row = ei;
    const int* col = ei + E;

    void *p_zero, *p_cx1, *p_cx2, *p_cx3, *p_cs1, *p_cs2, *p_cs3, *p_d1h, *p_d2h, *p_d3h;
    cudaGetSymbolAddress(&p_zero, g_zero3);
    cudaGetSymbolAddress(&p_cx1, g_cx1);
    cudaGetSymbolAddress(&p_cx2, g_cx2);
    cudaGetSymbolAddress(&p_cx3, g_cx3);
    cudaGetSymbolAddress(&p_cs1, g_cs1);
    cudaGetSymbolAddress(&p_cs2, g_cs2);
    cudaGetSymbolAddress(&p_cs3, g_cs3);
    cudaGetSymbolAddress(&p_d1h, g_d1h);
    cudaGetSymbolAddress(&p_d2h, g_d2h);
    cudaGetSymbolAddress(&p_d3h, g_d3h);

    cudaMemsetAsync(p_zero, 0, (3 * NMAX + 32) * sizeof(unsigned int), 0);

    int eb = (E + 255) / 256;
    int NL = N * 32;
    int xb = (NL + 255) / 256;
    int pb = (N + 3) / 4;    // pass1/pass4: 4 nodes per 64-thr block
    int mb = (N + 1) / 2;    // mid: 2 nodes per 64-thr block
    int sb = (N + 511) / 512;

    k_deg_xh<<<eb + xb, 256>>>(row, col, ew, (const float4*)X, E, NL, eb);
    k_scan12<<<sb, 512>>>(N, sb);
    k_scatter<<<eb, 256>>>(row, col, ew, E, N);

    k_pass1<<<pb, 64>>>((const float4*)X, N);   // 4th launch -> ncu capture
    k_mid<<<mb, 64>>>((const uint4*)p_cx1, (const uint4*)p_cs1,
                      (uint4*)p_cx2, (uint4*)p_cs2, (uint4*)p_d1h, N);
    k_mid<<<mb, 64>>>((const uint4*)p_cx2, (const uint4*)p_cs2,
                      (uint4*)p_cx3, (uint4*)p_cs3, (uint4*)p_d2h, N);
    k_pass4<<<pb, 64>>>((const uint4*)p_cs3, (uint4*)p_d3h, N);
    k_wt<<<D, D>>>(W1, W2);

    cudaFuncSetAttribute(k_epilogue, cudaFuncAttributeMaxDynamicSharedMemorySize, 65536);
    int gb = (N + 63) / 64;
    k_epilogue<<<gb, 256, 65536>>>((const float4*)X, (const float4*)av, mom,
                                   b1, b2, (float*)d_out, N);
}